// round 13
// baseline (speedup 1.0000x reference)
#include <cuda_runtime.h>
#include <cuda_bf16.h>
#include <math.h>
#include <stdint.h>

#define Bn 16
#define Hn 64
#define Wn 64
#define Cn 256
#define Nn 8
#define Dn 32
#define NROW (Bn*Hn*Wn)   // 65536

// ---------------- scratch (device globals; no allocation) ----------------
__device__ __nv_bfloat16 g_qh[NROW*Cn], g_ql[NROW*Cn];
__device__ __nv_bfloat16 g_kh[NROW*Cn], g_kl[NROW*Cn];
__device__ __nv_bfloat16 g_vh[NROW*Cn], g_vl[NROW*Cn];
__device__ float g_v[NROW*Cn];               // fp32 copy for lepe
__device__ float g_lepe[NROW*Cn];
__device__ float g_pre[NROW*Cn];
__device__ __nv_bfloat16 g_vwh[Bn*Hn*Nn*2048], g_vwl[Bn*Hn*Nn*2048];
__device__ __nv_bfloat16 g_v2h[Bn*Wn*Nn*2048], g_v2l[Bn*Wn*Nn*2048];
__device__ float g_da[Bn*Hn*Nn*Wn];
__device__ float g_db[Bn*Wn*Nn*Hn];
// P in MMA-fragment order
__device__ uint32_t g_qkwh[Bn*Hn*Nn*2048];
__device__ uint32_t g_qkwl[Bn*Hn*Nn*2048];

// bf16 hi/lo split buffers for projection GEMMs
__device__ __nv_bfloat16 g_ahi[NROW*Cn];
__device__ __nv_bfloat16 g_alo[NROW*Cn];
__device__ __nv_bfloat16 g_whi[4*Cn*Cn];
__device__ __nv_bfloat16 g_wlo[4*Cn*Cn];

// ---------------- helpers ----------------
__device__ __forceinline__ uint32_t smem_u32(const void* p) {
    uint32_t a;
    asm("{ .reg .u64 t; cvta.to.shared.u64 t, %1; cvt.u32.u64 %0, t; }"
        : "=r"(a) : "l"(p));
    return a;
}

__device__ __forceinline__ uint32_t pack_bf2(float a, float b) {
    return (uint32_t)__bfloat16_as_ushort(__float2bfloat16_rn(a))
         | ((uint32_t)__bfloat16_as_ushort(__float2bfloat16_rn(b)) << 16);
}

__device__ __forceinline__ void split4(float4 a, uint2& hv, uint2& lv) {
    float h0 = __bfloat162float(__float2bfloat16_rn(a.x));
    float h1 = __bfloat162float(__float2bfloat16_rn(a.y));
    float h2 = __bfloat162float(__float2bfloat16_rn(a.z));
    float h3 = __bfloat162float(__float2bfloat16_rn(a.w));
    hv.x = pack_bf2(a.x, a.y);
    hv.y = pack_bf2(a.z, a.w);
    lv.x = pack_bf2(a.x - h0, a.y - h1);
    lv.y = pack_bf2(a.z - h2, a.w - h3);
}

__device__ __forceinline__ void split1(float v, __nv_bfloat16& h, __nv_bfloat16& l) {
    h = __float2bfloat16_rn(v);
    l = __float2bfloat16_rn(v - __bfloat162float(h));
}

__device__ __forceinline__ uint32_t packsplit(float a, float b, uint32_t& lo) {
    __nv_bfloat16 ha, la, hb, lb;
    split1(a, ha, la);
    split1(b, hb, lb);
    lo = (uint32_t)__bfloat16_as_ushort(la) | ((uint32_t)__bfloat16_as_ushort(lb) << 16);
    return (uint32_t)__bfloat16_as_ushort(ha) | ((uint32_t)__bfloat16_as_ushort(hb) << 16);
}

__device__ __forceinline__ void ldm4(uint32_t addr, uint32_t& r0, uint32_t& r1,
                                     uint32_t& r2, uint32_t& r3) {
    asm volatile("ldmatrix.sync.aligned.m8n8.x4.shared.b16 {%0,%1,%2,%3}, [%4];"
                 : "=r"(r0), "=r"(r1), "=r"(r2), "=r"(r3) : "r"(addr));
}

__device__ __forceinline__ void ldm4t(uint32_t addr, uint32_t& r0, uint32_t& r1,
                                      uint32_t& r2, uint32_t& r3) {
    asm volatile("ldmatrix.sync.aligned.m8n8.x4.trans.shared.b16 {%0,%1,%2,%3}, [%4];"
                 : "=r"(r0), "=r"(r1), "=r"(r2), "=r"(r3) : "r"(addr));
}

__device__ __forceinline__ void mma16816(float* d, const uint32_t* a,
                                         uint32_t b0, uint32_t b1) {
    asm volatile("mma.sync.aligned.m16n8k16.row.col.f32.bf16.bf16.f32 "
                 "{%0,%1,%2,%3}, {%4,%5,%6,%7}, {%8,%9}, {%0,%1,%2,%3};"
                 : "+f"(d[0]), "+f"(d[1]), "+f"(d[2]), "+f"(d[3])
                 : "r"(a[0]), "r"(a[1]), "r"(a[2]), "r"(a[3]), "r"(b0), "r"(b1));
}

#define CPA16(dst, src) \
    asm volatile("cp.async.cg.shared.global [%0], [%1], 16;" \
                 :: "r"(dst), "l"(src) : "memory")

// ------------- fused: x -> bf16 hi/lo split  +  dt -> da/db -------------
__device__ __forceinline__ float softplusf(float a) {
    return (a > 20.f) ? a : log1pf(expf(a));
}

__global__ __launch_bounds__(256) void dtconv_kernel(
    const float* __restrict__ x, const float* __restrict__ dtw,
    const float* __restrict__ dtb, const float* __restrict__ Alog)
{
    int tid = threadIdx.x;
    int row_local = tid >> 6;
    int lane = tid & 31;
    int t64 = tid & 63;
    int c4 = t64 << 2;
    int r = blockIdx.x * 4 + row_local;
    size_t idx = (size_t)r * 256 + c4;

    float4 v = *(const float4*)(x + idx);
    uint2 hv, lv; split4(v, hv, lv);
    *(uint2*)(g_ahi + idx) = hv;
    *(uint2*)(g_alo + idx) = lv;

    int d4 = c4 & 31;
    float t0 = v.x * dtw[d4] + v.y * dtw[d4 + 1] + v.z * dtw[d4 + 2] + v.w * dtw[d4 + 3];
    float t1 = v.x * dtw[32 + d4] + v.y * dtw[32 + d4 + 1]
             + v.z * dtw[32 + d4 + 2] + v.w * dtw[32 + d4 + 3];
#pragma unroll
    for (int off = 4; off; off >>= 1) {
        t0 += __shfl_down_sync(0xffffffffu, t0, off);
        t1 += __shfl_down_sync(0xffffffffu, t1, off);
    }
    if ((lane & 7) == 0) {
        int n = t64 >> 3;
        int w = r & 63, h = (r >> 6) & 63, b = r >> 12;
        float bias = dtb[n];
        float Aa = -expf(Alog[n]);
        float da = softplusf(t0 + bias) * Aa;
        float db = softplusf(t1 + bias) * Aa;
        g_da[((b * 64 + h) * 8 + n) * 64 + w] = da;
        g_db[((b * 64 + w) * 8 + n) * 64 + h] = db;
    }
}

__global__ __launch_bounds__(256) void convW_kernel(
    const float* __restrict__ wq, const float* __restrict__ wk,
    const float* __restrict__ wv, const float* __restrict__ wo)
{
    const float* src = (blockIdx.y == 0) ? wq : (blockIdx.y == 1) ? wk
                     : (blockIdx.y == 2) ? wv : wo;
    size_t base = (size_t)blockIdx.y * 65536;
    size_t i = ((size_t)blockIdx.x * 256 + threadIdx.x) * 4;
    float4 v = *(const float4*)(src + i);
    uint2 hv, lv; split4(v, hv, lv);
    *(uint2*)(g_whi + base + i) = hv;
    *(uint2*)(g_wlo + base + i) = lv;
}

// ------------- projection GEMM -------------
#define GP 40
#define GMAT 10240
#define GSTG 40960
#define GEMM_SMEM (2*GSTG)

__global__ __launch_bounds__(256, 2) void gemm_mma_kernel(
    const float* __restrict__ b0p, const float* __restrict__ b1p,
    const float* __restrict__ b2p, float* __restrict__ dout,
    int mode, float scaleK,
    const float* __restrict__ sinp, const float* __restrict__ cosp)
{
    extern __shared__ char gsm[];
    int z, col;
    if (mode == 0) { z = blockIdx.x >> 1; col = blockIdx.x & 1; }
    else           { z = 3;               col = blockIdx.x; }
    __nv_bfloat16 *oh = nullptr, *ol = nullptr;
    const float* bias;
    float scale = 1.0f;
    bool do_rope = false;
    if (mode == 0) {
        if (z == 0)      { oh = g_qh; ol = g_ql; bias = b0p; do_rope = true; }
        else if (z == 1) { oh = g_kh; ol = g_kl; bias = b1p; do_rope = true; scale = scaleK; }
        else             { oh = g_vh; ol = g_vl; bias = b2p; }
    } else { bias = b0p; }
    const __nv_bfloat16* Whi = g_whi + (size_t)z * 65536;
    const __nv_bfloat16* Wlo = g_wlo + (size_t)z * 65536;

    int tid = threadIdx.x;
    int lane = tid & 31, wid = tid >> 5;
    int warp_m = wid >> 2, warp_n = wid & 3;
    int row0 = blockIdx.y * 128;
    int n0 = col * 128;

    int r0i = tid >> 2, q0 = tid & 3;
    int r1i = (tid + 256) >> 2, q1 = tid & 3;
    uint32_t st0 = (uint32_t)(r0i * GP + q0 * 8) * 2;
    uint32_t st1 = (uint32_t)(r1i * GP + q1 * 8) * 2;
    uint32_t gsb = smem_u32(gsm);

    float acc[4][4][4];
#pragma unroll
    for (int i = 0; i < 4; i++)
#pragma unroll
        for (int j = 0; j < 4; j++)
#pragma unroll
            for (int e = 0; e < 4; e++) acc[i][j][e] = 0.f;

    uint32_t a_off[4], b_off[2];
#pragma unroll
    for (int mi = 0; mi < 4; mi++) {
        int row = warp_m * 64 + mi * 16 + (lane & 15);
        int colb = ((lane >> 4) & 1) << 3;
        a_off[mi] = (uint32_t)(row * GP + colb) * 2;
    }
#pragma unroll
    for (int p = 0; p < 2; p++) {
        int m = lane >> 3;
        int nrow = warp_n * 32 + p * 16 + ((m >> 1) << 3) + (lane & 7);
        int colb = (m & 1) << 3;
        b_off[p] = (uint32_t)(nrow * GP + colb) * 2;
    }

    auto issue = [&](int kc) {
        uint32_t sb = gsb + (kc & 1) * GSTG;
        int kn = kc * 32;
        size_t a0 = (size_t)(row0 + r0i) * 256 + kn + q0 * 8;
        size_t a1 = (size_t)(row0 + r1i) * 256 + kn + q1 * 8;
        size_t b0 = (size_t)(n0 + r0i) * 256 + kn + q0 * 8;
        size_t b1 = (size_t)(n0 + r1i) * 256 + kn + q1 * 8;
        CPA16(sb + 0*GMAT + st0, (const void*)(g_ahi + a0));
        CPA16(sb + 0*GMAT + st1, (const void*)(g_ahi + a1));
        CPA16(sb + 1*GMAT + st0, (const void*)(g_alo + a0));
        CPA16(sb + 1*GMAT + st1, (const void*)(g_alo + a1));
        CPA16(sb + 2*GMAT + st0, (const void*)(Whi + b0));
        CPA16(sb + 2*GMAT + st1, (const void*)(Whi + b1));
        CPA16(sb + 3*GMAT + st0, (const void*)(Wlo + b0));
        CPA16(sb + 3*GMAT + st1, (const void*)(Wlo + b1));
        asm volatile("cp.async.commit_group;" ::: "memory");
    };

    issue(0);
    for (int kc = 0; kc < 8; kc++) {
        if (kc < 7) {
            issue(kc + 1);
            asm volatile("cp.async.wait_group 1;" ::: "memory");
        } else {
            asm volatile("cp.async.wait_group 0;" ::: "memory");
        }
        __syncthreads();
        uint32_t sb = gsb + (kc & 1) * GSTG;
#pragma unroll
        for (int ks = 0; ks < 2; ks++) {
            uint32_t kb = (uint32_t)(ks * 16) * 2;
            uint32_t bh[2][4], bl[2][4];
#pragma unroll
            for (int p = 0; p < 2; p++) {
                ldm4(sb + 2*GMAT + b_off[p] + kb, bh[p][0], bh[p][1], bh[p][2], bh[p][3]);
                ldm4(sb + 3*GMAT + b_off[p] + kb, bl[p][0], bl[p][1], bl[p][2], bl[p][3]);
            }
#pragma unroll
            for (int mi = 0; mi < 4; mi++) {
                uint32_t ah[4], al[4];
                ldm4(sb + 0*GMAT + a_off[mi] + kb, ah[0], ah[1], ah[2], ah[3]);
                ldm4(sb + 1*GMAT + a_off[mi] + kb, al[0], al[1], al[2], al[3]);
#pragma unroll
                for (int nj = 0; nj < 4; nj++) {
                    int p = nj >> 1, h = (nj & 1) << 1;
                    mma16816(acc[mi][nj], ah, bh[p][h], bh[p][h + 1]);
                    mma16816(acc[mi][nj], ah, bl[p][h], bl[p][h + 1]);
                    mma16816(acc[mi][nj], al, bh[p][h], bh[p][h + 1]);
                }
            }
        }
        __syncthreads();
    }

#pragma unroll
    for (int mi = 0; mi < 4; mi++) {
        int rbase = row0 + warp_m * 64 + mi * 16 + (lane >> 2);
        int hw0 = rbase & 4095;
        int hw8 = (rbase + 8) & 4095;
#pragma unroll
        for (int nj = 0; nj < 4; nj++) {
            int c = n0 + warp_n * 32 + nj * 8 + ((lane & 3) << 1);
            float b0 = __ldg(bias + c), b1 = __ldg(bias + c + 1);
            float2 o0, o1;
            o0.x = (acc[mi][nj][0] + b0) * scale;
            o0.y = (acc[mi][nj][1] + b1) * scale;
            o1.x = (acc[mi][nj][2] + b0) * scale;
            o1.y = (acc[mi][nj][3] + b1) * scale;
            if (do_rope) {
                int d0 = c & 31;
                float s0 = __ldg(sinp + hw0 * 32 + d0);
                float s1 = __ldg(sinp + hw0 * 32 + d0 + 1);
                float c0v = __ldg(cosp + hw0 * 32 + d0);
                float c1v = __ldg(cosp + hw0 * 32 + d0 + 1);
                float xe = o0.x, xo = o0.y;
                o0.x = xe * c0v - xo * s0;
                o0.y = xo * c1v + xe * s1;
                float s0b = __ldg(sinp + hw8 * 32 + d0);
                float s1b = __ldg(sinp + hw8 * 32 + d0 + 1);
                float c0b = __ldg(cosp + hw8 * 32 + d0);
                float c1b = __ldg(cosp + hw8 * 32 + d0 + 1);
                float xe1 = o1.x, xo1 = o1.y;
                o1.x = xe1 * c0b - xo1 * s0b;
                o1.y = xo1 * c1b + xe1 * s1b;
            }
            size_t e0 = (size_t)rbase * 256 + c;
            size_t e1 = (size_t)(rbase + 8) * 256 + c;
            if (mode == 1) {
                *(float2*)(dout + e0) = o0;
                *(float2*)(dout + e1) = o1;
            } else {
                uint32_t lo0, lo1;
                uint32_t hi0 = packsplit(o0.x, o0.y, lo0);
                uint32_t hi1 = packsplit(o1.x, o1.y, lo1);
                *(uint32_t*)(oh + e0) = hi0; *(uint32_t*)(ol + e0) = lo0;
                *(uint32_t*)(oh + e1) = hi1; *(uint32_t*)(ol + e1) = lo1;
                if (z == 2) {
                    *(float2*)(g_v + e0) = o0;
                    *(float2*)(g_v + e1) = o1;
                }
            }
        }
    }
}

// ---------------- LePE depthwise 5x5 conv ----------------
__global__ __launch_bounds__(256) void lepe_kernel(
    const float* __restrict__ lw, const float* __restrict__ lb)
{
    int blk = blockIdx.x;
    int whalf = blk & 1;
    int h = (blk >> 1) & 63;
    int b = blk >> 7;
    int c = threadIdx.x;

    float wt[5][5];
    const float* vrow[5];
    bool rv[5];
#pragma unroll
    for (int ki = 0; ki < 5; ki++) {
        int hh = h + ki - 2;
        rv[ki] = ((unsigned)hh < 64u);
        vrow[ki] = g_v + ((size_t)((b * 64 + (rv[ki] ? hh : 0)) * 64)) * 256 + c;
#pragma unroll
        for (int kj = 0; kj < 5; kj++)
            wt[ki][kj] = __ldg(lw + (ki * 5 + kj) * 256 + c);
    }
    float lbv = __ldg(lb + c);

    float win[5][5];
    int w0 = whalf * 32;
#pragma unroll
    for (int dj = 0; dj < 4; dj++) {
        int col = w0 - 2 + dj;
        bool cv = ((unsigned)col < 64u);
#pragma unroll
        for (int ki = 0; ki < 5; ki++)
            win[ki][dj] = (rv[ki] && cv) ? __ldg(vrow[ki] + col * 256) : 0.f;
    }

    float* outb = g_lepe + ((size_t)((b * 64 + h) * 64)) * 256 + c;
#pragma unroll
    for (int it = 0; it < 32; it++) {
        int w = w0 + it;
        int col = w + 2;
        bool cv = (col < 64);
        const int slot = (it + 4) % 5;
#pragma unroll
        for (int ki = 0; ki < 5; ki++)
            win[ki][slot] = (rv[ki] && cv) ? __ldg(vrow[ki] + col * 256) : 0.f;
        float acc = lbv;
#pragma unroll
        for (int ki = 0; ki < 5; ki++)
#pragma unroll
            for (int kj = 0; kj < 5; kj++)
                acc += win[ki][(it + kj) % 5] * wt[ki][kj];
        outb[w * 256] = acc;
    }
}

// ---------------- attention: 4-warp register-resident S/P ----------------
#define AQ_HI 0
#define AQ_LO 5120
#define AK_HI 10240
#define AK_LO 15360
#define AV_HI 20480
#define AV_LO 25600
#define AW_HI 30720
#define AW_LO 35840
#define W_CS  30720
#define H_CS  40960
#define ATTN_SMEM_W 30976
#define ATTN_SMEM_H 41216

// cs = inclusive prefix sum of 64 values (warp 0)
__device__ __forceinline__ void cs_scan(const float* __restrict__ src, float* cs, int tid)
{
    if (tid < 32) {
        float a = src[tid], b = src[tid + 32];
#pragma unroll
        for (int off = 1; off < 32; off <<= 1) {
            float t = __shfl_up_sync(0xffffffffu, a, off);
            if (tid >= off) a += t;
        }
        float tot = __shfl_sync(0xffffffffu, a, 31);
#pragma unroll
        for (int off = 1; off < 32; off <<= 1) {
            float t = __shfl_up_sync(0xffffffffu, b, off);
            if (tid >= off) b += t;
        }
        cs[tid] = a;
        cs[tid + 32] = b + tot;
    }
}

__device__ __forceinline__ void s_reg(uint32_t sbase, int lane, int w, float sacc[8][4])
{
    uint32_t a_off = (uint32_t)((w * 16 + (lane & 15)) * GP + (((lane >> 4) & 1) << 3)) * 2;
    int m = lane >> 3;
    uint32_t b_base = (uint32_t)((((m >> 1) << 3) + (lane & 7)) * GP + ((m & 1) << 3)) * 2;
#pragma unroll
    for (int ks = 0; ks < 2; ks++) {
        uint32_t kb = (uint32_t)ks * 32;
        uint32_t ah[4], al[4];
        ldm4(sbase + AQ_HI + a_off + kb, ah[0], ah[1], ah[2], ah[3]);
        ldm4(sbase + AQ_LO + a_off + kb, al[0], al[1], al[2], al[3]);
#pragma unroll
        for (int jb = 0; jb < 4; jb++) {
            uint32_t boff = b_base + (uint32_t)(jb * 16 * GP) * 2 + kb;
            uint32_t bh[4], bl[4];
            ldm4(sbase + AK_HI + boff, bh[0], bh[1], bh[2], bh[3]);
            ldm4(sbase + AK_LO + boff, bl[0], bl[1], bl[2], bl[3]);
#pragma unroll
            for (int half = 0; half < 2; half++) {
                float* d = sacc[jb * 2 + half];
                int h2 = half * 2;
                mma16816(d, ah, bh[h2], bh[h2 + 1]);
                mma16816(d, ah, bl[h2], bl[h2 + 1]);
                mma16816(d, al, bh[h2], bh[h2 + 1]);
            }
        }
    }
}

__device__ __forceinline__ void mask_softmax_reg(int lane, int w, const float* cs,
                                                 float sacc[8][4])
{
    int gr = lane >> 2, gc2 = (lane & 3) << 1;
    int r0 = w * 16 + gr, r1 = r0 + 8;
    float cr0 = cs[r0], cr1 = cs[r1];
#pragma unroll
    for (int nj = 0; nj < 8; nj++) {
        int c0 = nj * 8 + gc2;
        float cc0 = cs[c0], cc1 = cs[c0 + 1];
        sacc[nj][0] += (r0 >= c0)     ? cr0 - cc0 : cc0 - cr0;
        sacc[nj][1] += (r0 >= c0 + 1) ? cr0 - cc1 : cc1 - cr0;
        sacc[nj][2] += (r1 >= c0)     ? cr1 - cc0 : cc0 - cr1;
        sacc[nj][3] += (r1 >= c0 + 1) ? cr1 - cc1 : cc1 - cr1;
    }
    float m0 = -1e30f, m1 = -1e30f;
#pragma unroll
    for (int nj = 0; nj < 8; nj++) {
        m0 = fmaxf(m0, fmaxf(sacc[nj][0], sacc[nj][1]));
        m1 = fmaxf(m1, fmaxf(sacc[nj][2], sacc[nj][3]));
    }
    m0 = fmaxf(m0, __shfl_xor_sync(0xffffffffu, m0, 1));
    m0 = fmaxf(m0, __shfl_xor_sync(0xffffffffu, m0, 2));
    m1 = fmaxf(m1, __shfl_xor_sync(0xffffffffu, m1, 1));
    m1 = fmaxf(m1, __shfl_xor_sync(0xffffffffu, m1, 2));
    float s0 = 0.f, s1 = 0.f;
#pragma unroll
    for (int nj = 0; nj < 8; nj++) {
        sacc[nj][0] = __expf(sacc[nj][0] - m0); s0 += sacc[nj][0];
        sacc[nj][1] = __expf(sacc[nj][1] - m0); s0 += sacc[nj][1];
        sacc[nj][2] = __expf(sacc[nj][2] - m1); s1 += sacc[nj][2];
        sacc[nj][3] = __expf(sacc[nj][3] - m1); s1 += sacc[nj][3];
    }
    s0 += __shfl_xor_sync(0xffffffffu, s0, 1);
    s0 += __shfl_xor_sync(0xffffffffu, s0, 2);
    s1 += __shfl_xor_sync(0xffffffffu, s1, 1);
    s1 += __shfl_xor_sync(0xffffffffu, s1, 2);
    float i0 = 1.f / s0, i1 = 1.f / s1;
#pragma unroll
    for (int nj = 0; nj < 8; nj++) {
        sacc[nj][0] *= i0; sacc[nj][1] *= i0;
        sacc[nj][2] *= i1; sacc[nj][3] *= i1;
    }
}

__device__ __forceinline__ void pv_reg(uint32_t bhi, uint32_t blo, int lane,
                                       const uint32_t ph[8][2], const uint32_t pl[8][2],
                                       float facc[4][4])
{
    int g = lane >> 3, j8 = lane & 7;
    uint32_t b_base = (uint32_t)(((g & 1) * 8 + j8) * GP + ((g >> 1) << 3)) * 2;
#pragma unroll
    for (int kc = 0; kc < 4; kc++) {
        uint32_t ah[4] = {ph[2*kc][0], ph[2*kc][1], ph[2*kc+1][0], ph[2*kc+1][1]};
        uint32_t al[4] = {pl[2*kc][0], pl[2*kc][1], pl[2*kc+1][0], pl[2*kc+1][1]};
        uint32_t krow = (uint32_t)(kc * 16 * GP) * 2;
#pragma unroll
        for (int cg = 0; cg < 2; cg++) {
            uint32_t boff = b_base + krow + (uint32_t)(cg * 16) * 2;
            uint32_t bh[4], bl[4];
            ldm4t(bhi + boff, bh[0], bh[1], bh[2], bh[3]);
            ldm4t(blo + boff, bl[0], bl[1], bl[2], bl[3]);
#pragma unroll
            for (int half = 0; half < 2; half++) {
                float* d = facc[cg * 2 + half];
                int h2 = half * 2;
                mma16816(d, ah, bh[h2], bh[h2 + 1]);
                mma16816(d, ah, bl[h2], bl[h2 + 1]);
                mma16816(d, al, bh[h2], bh[h2 + 1]);
            }
        }
    }
}

__global__ __launch_bounds__(128) void attn_w_kernel(void)
{
    extern __shared__ char sm[];
    int blk = blockIdx.x;
    int n = blk & 7;
    int h = (blk >> 3) & 63;
    int b = blk >> 9;
    int tid = threadIdx.x, lane = tid & 31, w = tid >> 5;
    int qbase = ((b * 64 + h) * 64) * 256 + n * 32;
    float* cs = (float*)(sm + W_CS);
    uint32_t sbase = smem_u32(sm);

    for (int e = tid; e < 512; e += 128) {
        int i = e >> 3, d4 = (e & 7) << 2;
        size_t gi = (size_t)qbase + i * 256 + d4;
        uint32_t so = (uint32_t)(i * GP + d4) * 2;
        *(uint2*)(sm + AQ_HI + so) = *(const uint2*)(g_qh + gi);
        *(uint2*)(sm + AQ_LO + so) = *(const uint2*)(g_ql + gi);
        *(uint2*)(sm + AK_HI + so) = *(const uint2*)(g_kh + gi);
        *(uint2*)(sm + AK_LO + so) = *(const uint2*)(g_kl + gi);
        *(uint2*)(sm + AV_HI + so) = *(const uint2*)(g_vh + gi);
        *(uint2*)(sm + AV_LO + so) = *(const uint2*)(g_vl + gi);
    }
    cs_scan(g_da + blk * 64, cs, tid);
    __syncthreads();

    float sacc[8][4];
#pragma unroll
    for (int nj = 0; nj < 8; nj++)
#pragma unroll
        for (int e = 0; e < 4; e++) sacc[nj][e] = 0.f;
    s_reg(sbase, lane, w, sacc);
    mask_softmax_reg(lane, w, cs, sacc);

    uint32_t ph[8][2], pl[8][2];
    size_t pbase = (size_t)blk * 2048 + w * 512 + lane;
#pragma unroll
    for (int nj = 0; nj < 8; nj++) {
        ph[nj][0] = packsplit(sacc[nj][0], sacc[nj][1], pl[nj][0]);
        ph[nj][1] = packsplit(sacc[nj][2], sacc[nj][3], pl[nj][1]);
        g_qkwh[pbase + (nj * 2 + 0) * 32] = ph[nj][0];
        g_qkwh[pbase + (nj * 2 + 1) * 32] = ph[nj][1];
        g_qkwl[pbase + (nj * 2 + 0) * 32] = pl[nj][0];
        g_qkwl[pbase + (nj * 2 + 1) * 32] = pl[nj][1];
    }

    float facc[4][4];
#pragma unroll
    for (int nj = 0; nj < 4; nj++)
#pragma unroll
        for (int e = 0; e < 4; e++) facc[nj][e] = 0.f;
    pv_reg(sbase + AV_HI, sbase + AV_LO, lane, ph, pl, facc);

    size_t vwbase = (size_t)blk * 2048;
    int gr = lane >> 2, gc2 = (lane & 3) << 1;
    int r0 = w * 16 + gr;
#pragma unroll
    for (int nj = 0; nj < 4; nj++) {
        int d0 = nj * 8 + gc2;
        uint32_t lo0, lo1;
        uint32_t hi0 = packsplit(facc[nj][0], facc[nj][1], lo0);
        uint32_t hi1 = packsplit(facc[nj][2], facc[nj][3], lo1);
        *(uint32_t*)(g_vwh + vwbase + r0 * 32 + d0) = hi0;
        *(uint32_t*)(g_vwl + vwbase + r0 * 32 + d0) = lo0;
        *(uint32_t*)(g_vwh + vwbase + (r0 + 8) * 32 + d0) = hi1;
        *(uint32_t*)(g_vwl + vwbase + (r0 + 8) * 32 + d0) = lo1;
    }
}

__global__ __launch_bounds__(128) void attn_h_kernel(void)
{
    extern __shared__ char sm[];
    int blk = blockIdx.x;
    int n = blk & 7;
    int x = (blk >> 3) & 63;
    int b = blk >> 9;
    int tid = threadIdx.x, lane = tid & 31, w = tid >> 5;
    int qbase = (b * 64 * 64 + x) * 256 + n * 32;
    float* cs = (float*)(sm + H_CS);
    uint32_t sbase = smem_u32(sm);

    for (int e = tid; e < 512; e += 128) {
        int i = e >> 3, d4 = (e & 7) << 2;
        size_t gi = (size_t)qbase + (size_t)i * 16384 + d4;
        size_t wv = ((size_t)((b * 64 + i) * 8 + n)) * 2048 + x * 32 + d4;
        uint32_t so = (uint32_t)(i * GP + d4) * 2;
        *(uint2*)(sm + AQ_HI + so) = *(const uint2*)(g_qh + gi);
        *(uint2*)(sm + AQ_LO + so) = *(const uint2*)(g_ql + gi);
        *(uint2*)(sm + AK_HI + so) = *(const uint2*)(g_kh + gi);
        *(uint2*)(sm + AK_LO + so) = *(const uint2*)(g_kl + gi);
        *(uint2*)(sm + AV_HI + so) = *(const uint2*)(g_vh + gi);
        *(uint2*)(sm + AV_LO + so) = *(const uint2*)(g_vl + gi);
        *(uint2*)(sm + AW_HI + so) = *(const uint2*)(g_vwh + wv);
        *(uint2*)(sm + AW_LO + so) = *(const uint2*)(g_vwl + wv);
    }
    cs_scan(g_db + blk * 64, cs, tid);
    __syncthreads();

    float sacc[8][4];
#pragma unroll
    for (int nj = 0; nj < 8; nj++)
#pragma unroll
        for (int e = 0; e < 4; e++) sacc[nj][e] = 0.f;
    s_reg(sbase, lane, w, sacc);
    mask_softmax_reg(lane, w, cs, sacc);

    uint32_t ph[8][2], pl[8][2];
#pragma unroll
    for (int nj = 0; nj < 8; nj++) {
        ph[nj][0] = packsplit(sacc[nj][0], sacc[nj][1], pl[nj][0]);
        ph[nj][1] = packsplit(sacc[nj][2], sacc[nj][3], pl[nj][1]);
    }

    float facc1[4][4], facc2[4][4];
#pragma unroll
    for (int nj = 0; nj < 4; nj++)
#pragma unroll
        for (int e = 0; e < 4; e++) { facc1[nj][e] = 0.f; facc2[nj][e] = 0.f; }
    pv_reg(sbase + AV_HI, sbase + AV_LO, lane, ph, pl, facc1);
    pv_reg(sbase + AW_HI, sbase + AW_LO, lane, ph, pl, facc2);

    size_t v2base = (size_t)blk * 2048;
    int gr = lane >> 2, gc2 = (lane & 3) << 1;
    int r0 = w * 16 + gr;
#pragma unroll
    for (int nj = 0; nj < 4; nj++) {
        int d0 = nj * 8 + gc2;
        uint32_t lo0, lo1;
        uint32_t hi0 = packsplit(facc1[nj][0], facc1[nj][1], lo0);
        uint32_t hi1 = packsplit(facc1[nj][2], facc1[nj][3], lo1);
        *(uint32_t*)(g_v2h + v2base + r0 * 32 + d0) = hi0;
        *(uint32_t*)(g_v2l + v2base + r0 * 32 + d0) = lo0;
        *(uint32_t*)(g_v2h + v2base + (r0 + 8) * 32 + d0) = hi1;
        *(uint32_t*)(g_v2l + v2base + (r0 + 8) * 32 + d0) = lo1;
        float2 p0 = {0.5f * facc2[nj][0], 0.5f * facc2[nj][1]};
        float2 p1 = {0.5f * facc2[nj][2], 0.5f * facc2[nj][3]};
        *(float2*)(g_pre + (size_t)((b * 64 + r0) * 64 + x) * 256 + n * 32 + d0) = p0;
        *(float2*)(g_pre + (size_t)((b * 64 + r0 + 8) * 64 + x) * 256 + n * 32 + d0) = p1;
    }
}

// out2: final = pre + 0.5*(qk_w @ v_h2) + lepe -> bf16 hi/lo split
#define O2_VHI 0
#define O2_VLO 5120
#define OUT2_SMEM 10240

__global__ __launch_bounds__(128) void out2_kernel(void)
{
    extern __shared__ char sm[];
    int blk = blockIdx.x;
    int n = blk & 7;
    int y = (blk >> 3) & 63;
    int b = blk >> 9;
    int tid = threadIdx.x, lane = tid & 31, w = tid >> 5;
    uint32_t sbase = smem_u32(sm);

    uint32_t ph[8][2], pl[8][2];
    size_t pbase = (size_t)blk * 2048 + w * 512 + lane;
#pragma unroll
    for (int nj = 0; nj < 8; nj++) {
        ph[nj][0] = g_qkwh[pbase + (nj * 2 + 0) * 32];
        ph[nj][1] = g_qkwh[pbase + (nj * 2 + 1) * 32];
        pl[nj][0] = g_qkwl[pbase + (nj * 2 + 0) * 32];
        pl[nj][1] = g_qkwl[pbase + (nj * 2 + 1) * 32];
    }

    for (int e = tid; e < 512; e += 128) {
        int j = e >> 3, d4 = (e & 7) << 2;
        size_t gv = ((size_t)((b * 64 + j) * 8 + n)) * 2048 + y * 32 + d4;
        uint32_t so = (uint32_t)(j * GP + d4) * 2;
        *(uint2*)(sm + O2_VHI + so) = *(const uint2*)(g_v2h + gv);
        *(uint2*)(sm + O2_VLO + so) = *(const uint2*)(g_v2l + gv);
    }
    __syncthreads();

    float facc[4][4];
#pragma unroll
    for (int nj = 0; nj < 4; nj++)
#pragma unroll
        for (int e = 0; e < 4; e++) facc[nj][e] = 0.f;
    pv_reg(sbase + O2_VHI, sbase + O2_VLO, lane, ph, pl, facc);

    int gr = lane >> 2, gc2 = (lane & 3) << 1;
    int r0 = w * 16 + gr;
#pragma unroll
    for (int nj = 0; nj < 4; nj++) {
        int d0 = n * 32 + nj * 8 + gc2;
        size_t a0 = (size_t)((b * 64 + y) * 64 + r0) * 256 + d0;
        size_t a1 = (size_t)((b * 64 + y) * 64 + r0 + 8) * 256 + d0;
        float2 pr0 = *(float2*)(g_pre + a0);
        float2 le0 = *(float2*)(g_lepe + a0);
        float2 pr1 = *(float2*)(g_pre + a1);
        float2 le1 = *(float2*)(g_lepe + a1);
        float fx0 = pr0.x + 0.5f * facc[nj][0] + le0.x;
        float fy0 = pr0.y + 0.5f * facc[nj][1] + le0.y;
        float fx1 = pr1.x + 0.5f * facc[nj][2] + le1.x;
        float fy1 = pr1.y + 0.5f * facc[nj][3] + le1.y;
        uint32_t lo0, lo1;
        uint32_t hi0 = packsplit(fx0, fy0, lo0);
        uint32_t hi1 = packsplit(fx1, fy1, lo1);
        *(uint32_t*)(g_ahi + a0) = hi0;
        *(uint32_t*)(g_alo + a0) = lo0;
        *(uint32_t*)(g_ahi + a1) = hi1;
        *(uint32_t*)(g_alo + a1) = lo1;
    }
}

// ---------------- launch ----------------
extern "C" void kernel_launch(void* const* d_in, const int* in_sizes, int n_in,
                              void* d_out, int out_size)
{
    const float* x    = (const float*)d_in[0];
    const float* sinp = (const float*)d_in[1];
    const float* cosp = (const float*)d_in[2];
    const float* Wq   = (const float*)d_in[3];
    const float* bq   = (const float*)d_in[4];
    const float* Wk   = (const float*)d_in[5];
    const float* bk   = (const float*)d_in[6];
    const float* Wv   = (const float*)d_in[7];
    const float* bv   = (const float*)d_in[8];
    const float* Wo   = (const float*)d_in[9];
    const float* bo   = (const float*)d_in[10];
    const float* lw   = (const float*)d_in[11];
    const float* lb   = (const float*)d_in[12];
    const float* dtw  = (const float*)d_in[13];
    const float* dtb  = (const float*)d_in[14];
    const float* Alog = (const float*)d_in[15];
    float* out = (float*)d_out;

    const float scaling = 0.17677669529663687f;   // 32^-0.5

    cudaFuncSetAttribute(gemm_mma_kernel,
                         cudaFuncAttributeMaxDynamicSharedMemorySize, GEMM_SMEM);

    convW_kernel<<<dim3(64, 4), 256>>>(Wq, Wk, Wv, Wo);               // 0
    dtconv_kernel<<<NROW / 4, 256>>>(x, dtw, dtb, Alog);              // 1

    gemm_mma_kernel<<<dim3(6, 512), 256, GEMM_SMEM>>>(
        bq, bk, bv, nullptr, 0, scaling, sinp, cosp);                 // 2

    attn_w_kernel<<<Bn * Hn * Nn, 128, ATTN_SMEM_W>>>();              // 3 <- profiled
    attn_h_kernel<<<Bn * Wn * Nn, 128, ATTN_SMEM_H>>>();              // 4

    lepe_kernel<<<Bn * Hn * 2, 256>>>(lw, lb);                        // 5

    out2_kernel<<<Bn * Hn * Nn, 128, OUT2_SMEM>>>();                  // 6

    gemm_mma_kernel<<<dim3(2, 512), 256, GEMM_SMEM>>>(
        bo, nullptr, nullptr, out, 1, 1.0f, sinp, cosp);              // 7
}

// round 14
// speedup vs baseline: 1.0240x; 1.0240x over previous
#include <cuda_runtime.h>
#include <cuda_bf16.h>
#include <math.h>
#include <stdint.h>

#define Bn 16
#define Hn 64
#define Wn 64
#define Cn 256
#define Nn 8
#define Dn 32
#define NROW (Bn*Hn*Wn)   // 65536

// ---------------- scratch (device globals; no allocation) ----------------
__device__ __nv_bfloat16 g_qh[NROW*Cn], g_ql[NROW*Cn];
__device__ __nv_bfloat16 g_kh[NROW*Cn], g_kl[NROW*Cn];
__device__ float g_v[NROW*Cn];               // fp32 (lepe + attention split-on-load)
__device__ float g_lepe[NROW*Cn];
__device__ float g_pre[NROW*Cn];
__device__ __nv_bfloat16 g_vwh[Bn*Hn*Nn*2048], g_vwl[Bn*Hn*Nn*2048];
__device__ __nv_bfloat16 g_v2h[Bn*Wn*Nn*2048], g_v2l[Bn*Wn*Nn*2048];
__device__ float g_da[Bn*Hn*Nn*Wn];
__device__ float g_db[Bn*Wn*Nn*Hn];
// P in MMA-fragment order
__device__ uint32_t g_qkwh[Bn*Hn*Nn*2048];
__device__ uint32_t g_qkwl[Bn*Hn*Nn*2048];

// bf16 hi/lo split buffers for projection GEMMs
__device__ __nv_bfloat16 g_ahi[NROW*Cn];
__device__ __nv_bfloat16 g_alo[NROW*Cn];
__device__ __nv_bfloat16 g_whi[4*Cn*Cn];
__device__ __nv_bfloat16 g_wlo[4*Cn*Cn];

// ---------------- helpers ----------------
__device__ __forceinline__ uint32_t smem_u32(const void* p) {
    uint32_t a;
    asm("{ .reg .u64 t; cvta.to.shared.u64 t, %1; cvt.u32.u64 %0, t; }"
        : "=r"(a) : "l"(p));
    return a;
}

__device__ __forceinline__ uint32_t pack_bf2(float a, float b) {
    return (uint32_t)__bfloat16_as_ushort(__float2bfloat16_rn(a))
         | ((uint32_t)__bfloat16_as_ushort(__float2bfloat16_rn(b)) << 16);
}

__device__ __forceinline__ void split4(float4 a, uint2& hv, uint2& lv) {
    float h0 = __bfloat162float(__float2bfloat16_rn(a.x));
    float h1 = __bfloat162float(__float2bfloat16_rn(a.y));
    float h2 = __bfloat162float(__float2bfloat16_rn(a.z));
    float h3 = __bfloat162float(__float2bfloat16_rn(a.w));
    hv.x = pack_bf2(a.x, a.y);
    hv.y = pack_bf2(a.z, a.w);
    lv.x = pack_bf2(a.x - h0, a.y - h1);
    lv.y = pack_bf2(a.z - h2, a.w - h3);
}

__device__ __forceinline__ void split1(float v, __nv_bfloat16& h, __nv_bfloat16& l) {
    h = __float2bfloat16_rn(v);
    l = __float2bfloat16_rn(v - __bfloat162float(h));
}

__device__ __forceinline__ uint32_t packsplit(float a, float b, uint32_t& lo) {
    __nv_bfloat16 ha, la, hb, lb;
    split1(a, ha, la);
    split1(b, hb, lb);
    lo = (uint32_t)__bfloat16_as_ushort(la) | ((uint32_t)__bfloat16_as_ushort(lb) << 16);
    return (uint32_t)__bfloat16_as_ushort(ha) | ((uint32_t)__bfloat16_as_ushort(hb) << 16);
}

__device__ __forceinline__ void ldm4(uint32_t addr, uint32_t& r0, uint32_t& r1,
                                     uint32_t& r2, uint32_t& r3) {
    asm volatile("ldmatrix.sync.aligned.m8n8.x4.shared.b16 {%0,%1,%2,%3}, [%4];"
                 : "=r"(r0), "=r"(r1), "=r"(r2), "=r"(r3) : "r"(addr));
}

__device__ __forceinline__ void ldm4t(uint32_t addr, uint32_t& r0, uint32_t& r1,
                                      uint32_t& r2, uint32_t& r3) {
    asm volatile("ldmatrix.sync.aligned.m8n8.x4.trans.shared.b16 {%0,%1,%2,%3}, [%4];"
                 : "=r"(r0), "=r"(r1), "=r"(r2), "=r"(r3) : "r"(addr));
}

__device__ __forceinline__ void mma16816(float* d, const uint32_t* a,
                                         uint32_t b0, uint32_t b1) {
    asm volatile("mma.sync.aligned.m16n8k16.row.col.f32.bf16.bf16.f32 "
                 "{%0,%1,%2,%3}, {%4,%5,%6,%7}, {%8,%9}, {%0,%1,%2,%3};"
                 : "+f"(d[0]), "+f"(d[1]), "+f"(d[2]), "+f"(d[3])
                 : "r"(a[0]), "r"(a[1]), "r"(a[2]), "r"(a[3]), "r"(b0), "r"(b1));
}

#define CPA16(dst, src) \
    asm volatile("cp.async.cg.shared.global [%0], [%1], 16;" \
                 :: "r"(dst), "l"(src) : "memory")

// ------------- fused: x -> bf16 hi/lo split  +  dt -> da/db -------------
__device__ __forceinline__ float softplusf(float a) {
    return (a > 20.f) ? a : log1pf(expf(a));
}

__global__ __launch_bounds__(256) void dtconv_kernel(
    const float* __restrict__ x, const float* __restrict__ dtw,
    const float* __restrict__ dtb, const float* __restrict__ Alog)
{
    int tid = threadIdx.x;
    int row_local = tid >> 6;
    int lane = tid & 31;
    int t64 = tid & 63;
    int c4 = t64 << 2;
    int r = blockIdx.x * 4 + row_local;
    size_t idx = (size_t)r * 256 + c4;

    float4 v = *(const float4*)(x + idx);
    uint2 hv, lv; split4(v, hv, lv);
    *(uint2*)(g_ahi + idx) = hv;
    *(uint2*)(g_alo + idx) = lv;

    int d4 = c4 & 31;
    float t0 = v.x * dtw[d4] + v.y * dtw[d4 + 1] + v.z * dtw[d4 + 2] + v.w * dtw[d4 + 3];
    float t1 = v.x * dtw[32 + d4] + v.y * dtw[32 + d4 + 1]
             + v.z * dtw[32 + d4 + 2] + v.w * dtw[32 + d4 + 3];
#pragma unroll
    for (int off = 4; off; off >>= 1) {
        t0 += __shfl_down_sync(0xffffffffu, t0, off);
        t1 += __shfl_down_sync(0xffffffffu, t1, off);
    }
    if ((lane & 7) == 0) {
        int n = t64 >> 3;
        int w = r & 63, h = (r >> 6) & 63, b = r >> 12;
        float bias = dtb[n];
        float Aa = -expf(Alog[n]);
        float da = softplusf(t0 + bias) * Aa;
        float db = softplusf(t1 + bias) * Aa;
        g_da[((b * 64 + h) * 8 + n) * 64 + w] = da;
        g_db[((b * 64 + w) * 8 + n) * 64 + h] = db;
    }
}

__global__ __launch_bounds__(256) void convW_kernel(
    const float* __restrict__ wq, const float* __restrict__ wk,
    const float* __restrict__ wv, const float* __restrict__ wo)
{
    const float* src = (blockIdx.y == 0) ? wq : (blockIdx.y == 1) ? wk
                     : (blockIdx.y == 2) ? wv : wo;
    size_t base = (size_t)blockIdx.y * 65536;
    size_t i = ((size_t)blockIdx.x * 256 + threadIdx.x) * 4;
    float4 v = *(const float4*)(src + i);
    uint2 hv, lv; split4(v, hv, lv);
    *(uint2*)(g_whi + base + i) = hv;
    *(uint2*)(g_wlo + base + i) = lv;
}

// ------------- projection GEMM -------------
#define GP 40
#define GMAT 10240
#define GSTG 40960
#define GEMM_SMEM (2*GSTG)

__global__ __launch_bounds__(256, 2) void gemm_mma_kernel(
    const float* __restrict__ b0p, const float* __restrict__ b1p,
    const float* __restrict__ b2p, float* __restrict__ dout,
    int mode, float scaleK,
    const float* __restrict__ sinp, const float* __restrict__ cosp)
{
    extern __shared__ char gsm[];
    int z, col;
    if (mode == 0) { z = blockIdx.x >> 1; col = blockIdx.x & 1; }
    else           { z = 3;               col = blockIdx.x; }
    __nv_bfloat16 *oh = nullptr, *ol = nullptr;
    const float* bias;
    float scale = 1.0f;
    bool do_rope = false;
    if (mode == 0) {
        if (z == 0)      { oh = g_qh; ol = g_ql; bias = b0p; do_rope = true; }
        else if (z == 1) { oh = g_kh; ol = g_kl; bias = b1p; do_rope = true; scale = scaleK; }
        else             { bias = b2p; }
    } else { bias = b0p; }
    const __nv_bfloat16* Whi = g_whi + (size_t)z * 65536;
    const __nv_bfloat16* Wlo = g_wlo + (size_t)z * 65536;

    int tid = threadIdx.x;
    int lane = tid & 31, wid = tid >> 5;
    int warp_m = wid >> 2, warp_n = wid & 3;
    int row0 = blockIdx.y * 128;
    int n0 = col * 128;

    int r0i = tid >> 2, q0 = tid & 3;
    int r1i = (tid + 256) >> 2, q1 = tid & 3;
    uint32_t st0 = (uint32_t)(r0i * GP + q0 * 8) * 2;
    uint32_t st1 = (uint32_t)(r1i * GP + q1 * 8) * 2;
    uint32_t gsb = smem_u32(gsm);

    float acc[4][4][4];
#pragma unroll
    for (int i = 0; i < 4; i++)
#pragma unroll
        for (int j = 0; j < 4; j++)
#pragma unroll
            for (int e = 0; e < 4; e++) acc[i][j][e] = 0.f;

    uint32_t a_off[4], b_off[2];
#pragma unroll
    for (int mi = 0; mi < 4; mi++) {
        int row = warp_m * 64 + mi * 16 + (lane & 15);
        int colb = ((lane >> 4) & 1) << 3;
        a_off[mi] = (uint32_t)(row * GP + colb) * 2;
    }
#pragma unroll
    for (int p = 0; p < 2; p++) {
        int m = lane >> 3;
        int nrow = warp_n * 32 + p * 16 + ((m >> 1) << 3) + (lane & 7);
        int colb = (m & 1) << 3;
        b_off[p] = (uint32_t)(nrow * GP + colb) * 2;
    }

    auto issue = [&](int kc) {
        uint32_t sb = gsb + (kc & 1) * GSTG;
        int kn = kc * 32;
        size_t a0 = (size_t)(row0 + r0i) * 256 + kn + q0 * 8;
        size_t a1 = (size_t)(row0 + r1i) * 256 + kn + q1 * 8;
        size_t b0 = (size_t)(n0 + r0i) * 256 + kn + q0 * 8;
        size_t b1 = (size_t)(n0 + r1i) * 256 + kn + q1 * 8;
        CPA16(sb + 0*GMAT + st0, (const void*)(g_ahi + a0));
        CPA16(sb + 0*GMAT + st1, (const void*)(g_ahi + a1));
        CPA16(sb + 1*GMAT + st0, (const void*)(g_alo + a0));
        CPA16(sb + 1*GMAT + st1, (const void*)(g_alo + a1));
        CPA16(sb + 2*GMAT + st0, (const void*)(Whi + b0));
        CPA16(sb + 2*GMAT + st1, (const void*)(Whi + b1));
        CPA16(sb + 3*GMAT + st0, (const void*)(Wlo + b0));
        CPA16(sb + 3*GMAT + st1, (const void*)(Wlo + b1));
        asm volatile("cp.async.commit_group;" ::: "memory");
    };

    issue(0);
    for (int kc = 0; kc < 8; kc++) {
        if (kc < 7) {
            issue(kc + 1);
            asm volatile("cp.async.wait_group 1;" ::: "memory");
        } else {
            asm volatile("cp.async.wait_group 0;" ::: "memory");
        }
        __syncthreads();
        uint32_t sb = gsb + (kc & 1) * GSTG;
#pragma unroll
        for (int ks = 0; ks < 2; ks++) {
            uint32_t kb = (uint32_t)(ks * 16) * 2;
            uint32_t bh[2][4], bl[2][4];
#pragma unroll
            for (int p = 0; p < 2; p++) {
                ldm4(sb + 2*GMAT + b_off[p] + kb, bh[p][0], bh[p][1], bh[p][2], bh[p][3]);
                ldm4(sb + 3*GMAT + b_off[p] + kb, bl[p][0], bl[p][1], bl[p][2], bl[p][3]);
            }
#pragma unroll
            for (int mi = 0; mi < 4; mi++) {
                uint32_t ah[4], al[4];
                ldm4(sb + 0*GMAT + a_off[mi] + kb, ah[0], ah[1], ah[2], ah[3]);
                ldm4(sb + 1*GMAT + a_off[mi] + kb, al[0], al[1], al[2], al[3]);
#pragma unroll
                for (int nj = 0; nj < 4; nj++) {
                    int p = nj >> 1, h = (nj & 1) << 1;
                    mma16816(acc[mi][nj], ah, bh[p][h], bh[p][h + 1]);
                    mma16816(acc[mi][nj], ah, bl[p][h], bl[p][h + 1]);
                    mma16816(acc[mi][nj], al, bh[p][h], bh[p][h + 1]);
                }
            }
        }
        __syncthreads();
    }

#pragma unroll
    for (int mi = 0; mi < 4; mi++) {
        int rbase = row0 + warp_m * 64 + mi * 16 + (lane >> 2);
        int hw0 = rbase & 4095;
        int hw8 = (rbase + 8) & 4095;
#pragma unroll
        for (int nj = 0; nj < 4; nj++) {
            int c = n0 + warp_n * 32 + nj * 8 + ((lane & 3) << 1);
            float b0 = __ldg(bias + c), b1 = __ldg(bias + c + 1);
            float2 o0, o1;
            o0.x = (acc[mi][nj][0] + b0) * scale;
            o0.y = (acc[mi][nj][1] + b1) * scale;
            o1.x = (acc[mi][nj][2] + b0) * scale;
            o1.y = (acc[mi][nj][3] + b1) * scale;
            if (do_rope) {
                int d0 = c & 31;
                float s0 = __ldg(sinp + hw0 * 32 + d0);
                float s1 = __ldg(sinp + hw0 * 32 + d0 + 1);
                float c0v = __ldg(cosp + hw0 * 32 + d0);
                float c1v = __ldg(cosp + hw0 * 32 + d0 + 1);
                float xe = o0.x, xo = o0.y;
                o0.x = xe * c0v - xo * s0;
                o0.y = xo * c1v + xe * s1;
                float s0b = __ldg(sinp + hw8 * 32 + d0);
                float s1b = __ldg(sinp + hw8 * 32 + d0 + 1);
                float c0b = __ldg(cosp + hw8 * 32 + d0);
                float c1b = __ldg(cosp + hw8 * 32 + d0 + 1);
                float xe1 = o1.x, xo1 = o1.y;
                o1.x = xe1 * c0b - xo1 * s0b;
                o1.y = xo1 * c1b + xe1 * s1b;
            }
            size_t e0 = (size_t)rbase * 256 + c;
            size_t e1 = (size_t)(rbase + 8) * 256 + c;
            if (mode == 1) {
                *(float2*)(dout + e0) = o0;
                *(float2*)(dout + e1) = o1;
            } else if (z == 2) {
                *(float2*)(g_v + e0) = o0;
                *(float2*)(g_v + e1) = o1;
            } else {
                uint32_t lo0, lo1;
                uint32_t hi0 = packsplit(o0.x, o0.y, lo0);
                uint32_t hi1 = packsplit(o1.x, o1.y, lo1);
                *(uint32_t*)(oh + e0) = hi0; *(uint32_t*)(ol + e0) = lo0;
                *(uint32_t*)(oh + e1) = hi1; *(uint32_t*)(ol + e1) = lo1;
            }
        }
    }
}

// ---------------- LePE depthwise 5x5 conv ----------------
__global__ __launch_bounds__(256) void lepe_kernel(
    const float* __restrict__ lw, const float* __restrict__ lb)
{
    int blk = blockIdx.x;
    int whalf = blk & 1;
    int h = (blk >> 1) & 63;
    int b = blk >> 7;
    int c = threadIdx.x;

    float wt[5][5];
    const float* vrow[5];
    bool rv[5];
#pragma unroll
    for (int ki = 0; ki < 5; ki++) {
        int hh = h + ki - 2;
        rv[ki] = ((unsigned)hh < 64u);
        vrow[ki] = g_v + ((size_t)((b * 64 + (rv[ki] ? hh : 0)) * 64)) * 256 + c;
#pragma unroll
        for (int kj = 0; kj < 5; kj++)
            wt[ki][kj] = __ldg(lw + (ki * 5 + kj) * 256 + c);
    }
    float lbv = __ldg(lb + c);

    float win[5][5];
    int w0 = whalf * 32;
#pragma unroll
    for (int dj = 0; dj < 4; dj++) {
        int col = w0 - 2 + dj;
        bool cv = ((unsigned)col < 64u);
#pragma unroll
        for (int ki = 0; ki < 5; ki++)
            win[ki][dj] = (rv[ki] && cv) ? __ldg(vrow[ki] + col * 256) : 0.f;
    }

    float* outb = g_lepe + ((size_t)((b * 64 + h) * 64)) * 256 + c;
#pragma unroll
    for (int it = 0; it < 32; it++) {
        int w = w0 + it;
        int col = w + 2;
        bool cv = (col < 64);
        const int slot = (it + 4) % 5;
#pragma unroll
        for (int ki = 0; ki < 5; ki++)
            win[ki][slot] = (rv[ki] && cv) ? __ldg(vrow[ki] + col * 256) : 0.f;
        float acc = lbv;
#pragma unroll
        for (int ki = 0; ki < 5; ki++)
#pragma unroll
            for (int kj = 0; kj < 5; kj++)
                acc += win[ki][(it + kj) % 5] * wt[ki][kj];
        outb[w * 256] = acc;
    }
}

// ---------------- attention: 4-warp register-resident S/P ----------------
#define AQ_HI 0
#define AQ_LO 5120
#define AK_HI 10240
#define AK_LO 15360
#define AV_HI 20480
#define AV_LO 25600
#define AW_HI 30720
#define AW_LO 35840
#define W_CS  30720
#define H_CS  40960
#define ATTN_SMEM_W 30976
#define ATTN_SMEM_H 41216

__device__ __forceinline__ void cs_scan(const float* __restrict__ src, float* cs, int tid)
{
    if (tid < 32) {
        float a = src[tid], b = src[tid + 32];
#pragma unroll
        for (int off = 1; off < 32; off <<= 1) {
            float t = __shfl_up_sync(0xffffffffu, a, off);
            if (tid >= off) a += t;
        }
        float tot = __shfl_sync(0xffffffffu, a, 31);
#pragma unroll
        for (int off = 1; off < 32; off <<= 1) {
            float t = __shfl_up_sync(0xffffffffu, b, off);
            if (tid >= off) b += t;
        }
        cs[tid] = a;
        cs[tid + 32] = b + tot;
    }
}

__device__ __forceinline__ void s_reg(uint32_t sbase, int lane, int w, float sacc[8][4])
{
    uint32_t a_off = (uint32_t)((w * 16 + (lane & 15)) * GP + (((lane >> 4) & 1) << 3)) * 2;
    int m = lane >> 3;
    uint32_t b_base = (uint32_t)((((m >> 1) << 3) + (lane & 7)) * GP + ((m & 1) << 3)) * 2;
#pragma unroll
    for (int ks = 0; ks < 2; ks++) {
        uint32_t kb = (uint32_t)ks * 32;
        uint32_t ah[4], al[4];
        ldm4(sbase + AQ_HI + a_off + kb, ah[0], ah[1], ah[2], ah[3]);
        ldm4(sbase + AQ_LO + a_off + kb, al[0], al[1], al[2], al[3]);
#pragma unroll
        for (int jb = 0; jb < 4; jb++) {
            uint32_t boff = b_base + (uint32_t)(jb * 16 * GP) * 2 + kb;
            uint32_t bh[4], bl[4];
            ldm4(sbase + AK_HI + boff, bh[0], bh[1], bh[2], bh[3]);
            ldm4(sbase + AK_LO + boff, bl[0], bl[1], bl[2], bl[3]);
#pragma unroll
            for (int half = 0; half < 2; half++) {
                float* d = sacc[jb * 2 + half];
                int h2 = half * 2;
                mma16816(d, ah, bh[h2], bh[h2 + 1]);
                mma16816(d, ah, bl[h2], bl[h2 + 1]);
                mma16816(d, al, bh[h2], bh[h2 + 1]);
            }
        }
    }
}

__device__ __forceinline__ void mask_softmax_reg(int lane, int w, const float* cs,
                                                 float sacc[8][4])
{
    int gr = lane >> 2, gc2 = (lane & 3) << 1;
    int r0 = w * 16 + gr, r1 = r0 + 8;
    float cr0 = cs[r0], cr1 = cs[r1];
#pragma unroll
    for (int nj = 0; nj < 8; nj++) {
        int c0 = nj * 8 + gc2;
        float cc0 = cs[c0], cc1 = cs[c0 + 1];
        sacc[nj][0] += (r0 >= c0)     ? cr0 - cc0 : cc0 - cr0;
        sacc[nj][1] += (r0 >= c0 + 1) ? cr0 - cc1 : cc1 - cr0;
        sacc[nj][2] += (r1 >= c0)     ? cr1 - cc0 : cc0 - cr1;
        sacc[nj][3] += (r1 >= c0 + 1) ? cr1 - cc1 : cc1 - cr1;
    }
    float m0 = -1e30f, m1 = -1e30f;
#pragma unroll
    for (int nj = 0; nj < 8; nj++) {
        m0 = fmaxf(m0, fmaxf(sacc[nj][0], sacc[nj][1]));
        m1 = fmaxf(m1, fmaxf(sacc[nj][2], sacc[nj][3]));
    }
    m0 = fmaxf(m0, __shfl_xor_sync(0xffffffffu, m0, 1));
    m0 = fmaxf(m0, __shfl_xor_sync(0xffffffffu, m0, 2));
    m1 = fmaxf(m1, __shfl_xor_sync(0xffffffffu, m1, 1));
    m1 = fmaxf(m1, __shfl_xor_sync(0xffffffffu, m1, 2));
    float s0 = 0.f, s1 = 0.f;
#pragma unroll
    for (int nj = 0; nj < 8; nj++) {
        sacc[nj][0] = __expf(sacc[nj][0] - m0); s0 += sacc[nj][0];
        sacc[nj][1] = __expf(sacc[nj][1] - m0); s0 += sacc[nj][1];
        sacc[nj][2] = __expf(sacc[nj][2] - m1); s1 += sacc[nj][2];
        sacc[nj][3] = __expf(sacc[nj][3] - m1); s1 += sacc[nj][3];
    }
    s0 += __shfl_xor_sync(0xffffffffu, s0, 1);
    s0 += __shfl_xor_sync(0xffffffffu, s0, 2);
    s1 += __shfl_xor_sync(0xffffffffu, s1, 1);
    s1 += __shfl_xor_sync(0xffffffffu, s1, 2);
    float i0 = 1.f / s0, i1 = 1.f / s1;
#pragma unroll
    for (int nj = 0; nj < 8; nj++) {
        sacc[nj][0] *= i0; sacc[nj][1] *= i0;
        sacc[nj][2] *= i1; sacc[nj][3] *= i1;
    }
}

__device__ __forceinline__ void pv_reg(uint32_t bhi, uint32_t blo, int lane,
                                       const uint32_t ph[8][2], const uint32_t pl[8][2],
                                       float facc[4][4])
{
    int g = lane >> 3, j8 = lane & 7;
    uint32_t b_base = (uint32_t)(((g & 1) * 8 + j8) * GP + ((g >> 1) << 3)) * 2;
#pragma unroll
    for (int kc = 0; kc < 4; kc++) {
        uint32_t ah[4] = {ph[2*kc][0], ph[2*kc][1], ph[2*kc+1][0], ph[2*kc+1][1]};
        uint32_t al[4] = {pl[2*kc][0], pl[2*kc][1], pl[2*kc+1][0], pl[2*kc+1][1]};
        uint32_t krow = (uint32_t)(kc * 16 * GP) * 2;
#pragma unroll
        for (int cg = 0; cg < 2; cg++) {
            uint32_t boff = b_base + krow + (uint32_t)(cg * 16) * 2;
            uint32_t bh[4], bl[4];
            ldm4t(bhi + boff, bh[0], bh[1], bh[2], bh[3]);
            ldm4t(blo + boff, bl[0], bl[1], bl[2], bl[3]);
#pragma unroll
            for (int half = 0; half < 2; half++) {
                float* d = facc[cg * 2 + half];
                int h2 = half * 2;
                mma16816(d, ah, bh[h2], bh[h2 + 1]);
                mma16816(d, ah, bl[h2], bl[h2 + 1]);
                mma16816(d, al, bh[h2], bh[h2 + 1]);
            }
        }
    }
}

__global__ __launch_bounds__(128) void attn_w_kernel(void)
{
    extern __shared__ char sm[];
    int blk = blockIdx.x;
    int n = blk & 7;
    int h = (blk >> 3) & 63;
    int b = blk >> 9;
    int tid = threadIdx.x, lane = tid & 31, w = tid >> 5;
    int qbase = ((b * 64 + h) * 64) * 256 + n * 32;
    float* cs = (float*)(sm + W_CS);
    uint32_t sbase = smem_u32(sm);

    for (int e = tid; e < 512; e += 128) {
        int i = e >> 3, d4 = (e & 7) << 2;
        size_t gi = (size_t)qbase + i * 256 + d4;
        uint32_t so = (uint32_t)(i * GP + d4) * 2;
        *(uint2*)(sm + AQ_HI + so) = *(const uint2*)(g_qh + gi);
        *(uint2*)(sm + AQ_LO + so) = *(const uint2*)(g_ql + gi);
        *(uint2*)(sm + AK_HI + so) = *(const uint2*)(g_kh + gi);
        *(uint2*)(sm + AK_LO + so) = *(const uint2*)(g_kl + gi);
        float4 vv = *(const float4*)(g_v + gi);
        uint2 hv, lv; split4(vv, hv, lv);
        *(uint2*)(sm + AV_HI + so) = hv;
        *(uint2*)(sm + AV_LO + so) = lv;
    }
    cs_scan(g_da + blk * 64, cs, tid);
    __syncthreads();

    float sacc[8][4];
#pragma unroll
    for (int nj = 0; nj < 8; nj++)
#pragma unroll
        for (int e = 0; e < 4; e++) sacc[nj][e] = 0.f;
    s_reg(sbase, lane, w, sacc);
    mask_softmax_reg(lane, w, cs, sacc);

    uint32_t ph[8][2], pl[8][2];
    size_t pbase = (size_t)blk * 2048 + w * 512 + lane;
#pragma unroll
    for (int nj = 0; nj < 8; nj++) {
        ph[nj][0] = packsplit(sacc[nj][0], sacc[nj][1], pl[nj][0]);
        ph[nj][1] = packsplit(sacc[nj][2], sacc[nj][3], pl[nj][1]);
        g_qkwh[pbase + (nj * 2 + 0) * 32] = ph[nj][0];
        g_qkwh[pbase + (nj * 2 + 1) * 32] = ph[nj][1];
        g_qkwl[pbase + (nj * 2 + 0) * 32] = pl[nj][0];
        g_qkwl[pbase + (nj * 2 + 1) * 32] = pl[nj][1];
    }

    float facc[4][4];
#pragma unroll
    for (int nj = 0; nj < 4; nj++)
#pragma unroll
        for (int e = 0; e < 4; e++) facc[nj][e] = 0.f;
    pv_reg(sbase + AV_HI, sbase + AV_LO, lane, ph, pl, facc);

    size_t vwbase = (size_t)blk * 2048;
    int gr = lane >> 2, gc2 = (lane & 3) << 1;
    int r0 = w * 16 + gr;
#pragma unroll
    for (int nj = 0; nj < 4; nj++) {
        int d0 = nj * 8 + gc2;
        uint32_t lo0, lo1;
        uint32_t hi0 = packsplit(facc[nj][0], facc[nj][1], lo0);
        uint32_t hi1 = packsplit(facc[nj][2], facc[nj][3], lo1);
        *(uint32_t*)(g_vwh + vwbase + r0 * 32 + d0) = hi0;
        *(uint32_t*)(g_vwl + vwbase + r0 * 32 + d0) = lo0;
        *(uint32_t*)(g_vwh + vwbase + (r0 + 8) * 32 + d0) = hi1;
        *(uint32_t*)(g_vwl + vwbase + (r0 + 8) * 32 + d0) = lo1;
    }
}

__global__ __launch_bounds__(128) void attn_h_kernel(void)
{
    extern __shared__ char sm[];
    int blk = blockIdx.x;
    int n = blk & 7;
    int x = (blk >> 3) & 63;
    int b = blk >> 9;
    int tid = threadIdx.x, lane = tid & 31, w = tid >> 5;
    int qbase = (b * 64 * 64 + x) * 256 + n * 32;
    float* cs = (float*)(sm + H_CS);
    uint32_t sbase = smem_u32(sm);

    for (int e = tid; e < 512; e += 128) {
        int i = e >> 3, d4 = (e & 7) << 2;
        size_t gi = (size_t)qbase + (size_t)i * 16384 + d4;
        size_t wv = ((size_t)((b * 64 + i) * 8 + n)) * 2048 + x * 32 + d4;
        uint32_t so = (uint32_t)(i * GP + d4) * 2;
        *(uint2*)(sm + AQ_HI + so) = *(const uint2*)(g_qh + gi);
        *(uint2*)(sm + AQ_LO + so) = *(const uint2*)(g_ql + gi);
        *(uint2*)(sm + AK_HI + so) = *(const uint2*)(g_kh + gi);
        *(uint2*)(sm + AK_LO + so) = *(const uint2*)(g_kl + gi);
        float4 vv = *(const float4*)(g_v + gi);
        uint2 hv, lv; split4(vv, hv, lv);
        *(uint2*)(sm + AV_HI + so) = hv;
        *(uint2*)(sm + AV_LO + so) = lv;
        *(uint2*)(sm + AW_HI + so) = *(const uint2*)(g_vwh + wv);
        *(uint2*)(sm + AW_LO + so) = *(const uint2*)(g_vwl + wv);
    }
    cs_scan(g_db + blk * 64, cs, tid);
    __syncthreads();

    float sacc[8][4];
#pragma unroll
    for (int nj = 0; nj < 8; nj++)
#pragma unroll
        for (int e = 0; e < 4; e++) sacc[nj][e] = 0.f;
    s_reg(sbase, lane, w, sacc);
    mask_softmax_reg(lane, w, cs, sacc);

    uint32_t ph[8][2], pl[8][2];
#pragma unroll
    for (int nj = 0; nj < 8; nj++) {
        ph[nj][0] = packsplit(sacc[nj][0], sacc[nj][1], pl[nj][0]);
        ph[nj][1] = packsplit(sacc[nj][2], sacc[nj][3], pl[nj][1]);
    }

    float facc1[4][4], facc2[4][4];
#pragma unroll
    for (int nj = 0; nj < 4; nj++)
#pragma unroll
        for (int e = 0; e < 4; e++) { facc1[nj][e] = 0.f; facc2[nj][e] = 0.f; }
    pv_reg(sbase + AV_HI, sbase + AV_LO, lane, ph, pl, facc1);
    pv_reg(sbase + AW_HI, sbase + AW_LO, lane, ph, pl, facc2);

    size_t v2base = (size_t)blk * 2048;
    int gr = lane >> 2, gc2 = (lane & 3) << 1;
    int r0 = w * 16 + gr;
#pragma unroll
    for (int nj = 0; nj < 4; nj++) {
        int d0 = nj * 8 + gc2;
        uint32_t lo0, lo1;
        uint32_t hi0 = packsplit(facc1[nj][0], facc1[nj][1], lo0);
        uint32_t hi1 = packsplit(facc1[nj][2], facc1[nj][3], lo1);
        *(uint32_t*)(g_v2h + v2base + r0 * 32 + d0) = hi0;
        *(uint32_t*)(g_v2l + v2base + r0 * 32 + d0) = lo0;
        *(uint32_t*)(g_v2h + v2base + (r0 + 8) * 32 + d0) = hi1;
        *(uint32_t*)(g_v2l + v2base + (r0 + 8) * 32 + d0) = lo1;
        float2 p0 = {0.5f * facc2[nj][0], 0.5f * facc2[nj][1]};
        float2 p1 = {0.5f * facc2[nj][2], 0.5f * facc2[nj][3]};
        *(float2*)(g_pre + (size_t)((b * 64 + r0) * 64 + x) * 256 + n * 32 + d0) = p0;
        *(float2*)(g_pre + (size_t)((b * 64 + r0 + 8) * 64 + x) * 256 + n * 32 + d0) = p1;
    }
}

// out2: final = pre + 0.5*(qk_w @ v_h2) + lepe -> bf16 hi/lo split
#define O2_VHI 0
#define O2_VLO 5120
#define OUT2_SMEM 10240

__global__ __launch_bounds__(128) void out2_kernel(void)
{
    extern __shared__ char sm[];
    int blk = blockIdx.x;
    int n = blk & 7;
    int y = (blk >> 3) & 63;
    int b = blk >> 9;
    int tid = threadIdx.x, lane = tid & 31, w = tid >> 5;
    uint32_t sbase = smem_u32(sm);

    uint32_t ph[8][2], pl[8][2];
    size_t pbase = (size_t)blk * 2048 + w * 512 + lane;
#pragma unroll
    for (int nj = 0; nj < 8; nj++) {
        ph[nj][0] = g_qkwh[pbase + (nj * 2 + 0) * 32];
        ph[nj][1] = g_qkwh[pbase + (nj * 2 + 1) * 32];
        pl[nj][0] = g_qkwl[pbase + (nj * 2 + 0) * 32];
        pl[nj][1] = g_qkwl[pbase + (nj * 2 + 1) * 32];
    }

    for (int e = tid; e < 512; e += 128) {
        int j = e >> 3, d4 = (e & 7) << 2;
        size_t gv = ((size_t)((b * 64 + j) * 8 + n)) * 2048 + y * 32 + d4;
        uint32_t so = (uint32_t)(j * GP + d4) * 2;
        *(uint2*)(sm + O2_VHI + so) = *(const uint2*)(g_v2h + gv);
        *(uint2*)(sm + O2_VLO + so) = *(const uint2*)(g_v2l + gv);
    }
    __syncthreads();

    float facc[4][4];
#pragma unroll
    for (int nj = 0; nj < 4; nj++)
#pragma unroll
        for (int e = 0; e < 4; e++) facc[nj][e] = 0.f;
    pv_reg(sbase + O2_VHI, sbase + O2_VLO, lane, ph, pl, facc);

    int gr = lane >> 2, gc2 = (lane & 3) << 1;
    int r0 = w * 16 + gr;
#pragma unroll
    for (int nj = 0; nj < 4; nj++) {
        int d0 = n * 32 + nj * 8 + gc2;
        size_t a0 = (size_t)((b * 64 + y) * 64 + r0) * 256 + d0;
        size_t a1 = (size_t)((b * 64 + y) * 64 + r0 + 8) * 256 + d0;
        float2 pr0 = *(float2*)(g_pre + a0);
        float2 le0 = *(float2*)(g_lepe + a0);
        float2 pr1 = *(float2*)(g_pre + a1);
        float2 le1 = *(float2*)(g_lepe + a1);
        float fx0 = pr0.x + 0.5f * facc[nj][0] + le0.x;
        float fy0 = pr0.y + 0.5f * facc[nj][1] + le0.y;
        float fx1 = pr1.x + 0.5f * facc[nj][2] + le1.x;
        float fy1 = pr1.y + 0.5f * facc[nj][3] + le1.y;
        uint32_t lo0, lo1;
        uint32_t hi0 = packsplit(fx0, fy0, lo0);
        uint32_t hi1 = packsplit(fx1, fy1, lo1);
        *(uint32_t*)(g_ahi + a0) = hi0;
        *(uint32_t*)(g_alo + a0) = lo0;
        *(uint32_t*)(g_ahi + a1) = hi1;
        *(uint32_t*)(g_alo + a1) = lo1;
    }
}

// ---------------- launch ----------------
extern "C" void kernel_launch(void* const* d_in, const int* in_sizes, int n_in,
                              void* d_out, int out_size)
{
    const float* x    = (const float*)d_in[0];
    const float* sinp = (const float*)d_in[1];
    const float* cosp = (const float*)d_in[2];
    const float* Wq   = (const float*)d_in[3];
    const float* bq   = (const float*)d_in[4];
    const float* Wk   = (const float*)d_in[5];
    const float* bk   = (const float*)d_in[6];
    const float* Wv   = (const float*)d_in[7];
    const float* bv   = (const float*)d_in[8];
    const float* Wo   = (const float*)d_in[9];
    const float* bo   = (const float*)d_in[10];
    const float* lw   = (const float*)d_in[11];
    const float* lb   = (const float*)d_in[12];
    const float* dtw  = (const float*)d_in[13];
    const float* dtb  = (const float*)d_in[14];
    const float* Alog = (const float*)d_in[15];
    float* out = (float*)d_out;

    const float scaling = 0.17677669529663687f;   // 32^-0.5

    cudaFuncSetAttribute(gemm_mma_kernel,
                         cudaFuncAttributeMaxDynamicSharedMemorySize, GEMM_SMEM);

    convW_kernel<<<dim3(64, 4), 256>>>(Wq, Wk, Wv, Wo);               // 0
    dtconv_kernel<<<NROW / 4, 256>>>(x, dtw, dtb, Alog);              // 1

    gemm_mma_kernel<<<dim3(6, 512), 256, GEMM_SMEM>>>(
        bq, bk, bv, nullptr, 0, scaling, sinp, cosp);                 // 2

    attn_w_kernel<<<Bn * Hn * Nn, 128, ATTN_SMEM_W>>>();              // 3
    attn_h_kernel<<<Bn * Wn * Nn, 128, ATTN_SMEM_H>>>();              // 4 <- profiled
    lepe_kernel<<<Bn * Hn * 2, 256>>>(lw, lb);                        // 5

    out2_kernel<<<Bn * Hn * Nn, 128, OUT2_SMEM>>>();                  // 6

    gemm_mma_kernel<<<dim3(2, 512), 256, GEMM_SMEM>>>(
        bo, nullptr, nullptr, out, 1, 1.0f, sinp, cosp);              // 7
}

// round 15
// speedup vs baseline: 1.0850x; 1.0596x over previous
#include <cuda_runtime.h>
#include <cuda_bf16.h>
#include <math.h>
#include <stdint.h>

#define Bn 16
#define Hn 64
#define Wn 64
#define Cn 256
#define Nn 8
#define Dn 32
#define NROW (Bn*Hn*Wn)   // 65536

// ---------------- scratch (device globals; no allocation) ----------------
__device__ float g_q[NROW*Cn];
__device__ float g_k[NROW*Cn];
__device__ float g_v[NROW*Cn];
__device__ float g_lepe[NROW*Cn];
__device__ float g_pre[NROW*Cn];
__device__ float g_vw[Bn*Hn*Nn*64*32];       // [b][h][n][w][d]
__device__ float g_vh2[Bn*Wn*Nn*64*32];      // [b][w][n][h][d]
__device__ float g_da[Bn*Hn*Nn*Wn];
__device__ float g_db[Bn*Wn*Nn*Hn];
// P (hi only) in MMA-fragment order: [blk][warp(4)][nj*2+reg(16)][lane(32)]
__device__ uint32_t g_qkwh[Bn*Hn*Nn*2048];

// bf16 hi/lo split buffers for projection GEMMs
__device__ __nv_bfloat16 g_ahi[NROW*Cn];
__device__ __nv_bfloat16 g_alo[NROW*Cn];
__device__ __nv_bfloat16 g_whi[4*Cn*Cn];
__device__ __nv_bfloat16 g_wlo[4*Cn*Cn];

// ---------------- helpers ----------------
__device__ __forceinline__ uint32_t smem_u32(const void* p) {
    uint32_t a;
    asm("{ .reg .u64 t; cvta.to.shared.u64 t, %1; cvt.u32.u64 %0, t; }"
        : "=r"(a) : "l"(p));
    return a;
}

__device__ __forceinline__ uint32_t pack_bf2(float a, float b) {
    return (uint32_t)__bfloat16_as_ushort(__float2bfloat16_rn(a))
         | ((uint32_t)__bfloat16_as_ushort(__float2bfloat16_rn(b)) << 16);
}

__device__ __forceinline__ void split4(float4 a, uint2& hv, uint2& lv) {
    float h0 = __bfloat162float(__float2bfloat16_rn(a.x));
    float h1 = __bfloat162float(__float2bfloat16_rn(a.y));
    float h2 = __bfloat162float(__float2bfloat16_rn(a.z));
    float h3 = __bfloat162float(__float2bfloat16_rn(a.w));
    hv.x = pack_bf2(a.x, a.y);
    hv.y = pack_bf2(a.z, a.w);
    lv.x = pack_bf2(a.x - h0, a.y - h1);
    lv.y = pack_bf2(a.z - h2, a.w - h3);
}

__device__ __forceinline__ void split1(float v, __nv_bfloat16& h, __nv_bfloat16& l) {
    h = __float2bfloat16_rn(v);
    l = __float2bfloat16_rn(v - __bfloat162float(h));
}

__device__ __forceinline__ uint32_t packsplit(float a, float b, uint32_t& lo) {
    __nv_bfloat16 ha, la, hb, lb;
    split1(a, ha, la);
    split1(b, hb, lb);
    lo = (uint32_t)__bfloat16_as_ushort(la) | ((uint32_t)__bfloat16_as_ushort(lb) << 16);
    return (uint32_t)__bfloat16_as_ushort(ha) | ((uint32_t)__bfloat16_as_ushort(hb) << 16);
}

__device__ __forceinline__ void ldm4(uint32_t addr, uint32_t& r0, uint32_t& r1,
                                     uint32_t& r2, uint32_t& r3) {
    asm volatile("ldmatrix.sync.aligned.m8n8.x4.shared.b16 {%0,%1,%2,%3}, [%4];"
                 : "=r"(r0), "=r"(r1), "=r"(r2), "=r"(r3) : "r"(addr));
}

__device__ __forceinline__ void ldm4t(uint32_t addr, uint32_t& r0, uint32_t& r1,
                                      uint32_t& r2, uint32_t& r3) {
    asm volatile("ldmatrix.sync.aligned.m8n8.x4.trans.shared.b16 {%0,%1,%2,%3}, [%4];"
                 : "=r"(r0), "=r"(r1), "=r"(r2), "=r"(r3) : "r"(addr));
}

__device__ __forceinline__ void mma16816(float* d, const uint32_t* a,
                                         uint32_t b0, uint32_t b1) {
    asm volatile("mma.sync.aligned.m16n8k16.row.col.f32.bf16.bf16.f32 "
                 "{%0,%1,%2,%3}, {%4,%5,%6,%7}, {%8,%9}, {%0,%1,%2,%3};"
                 : "+f"(d[0]), "+f"(d[1]), "+f"(d[2]), "+f"(d[3])
                 : "r"(a[0]), "r"(a[1]), "r"(a[2]), "r"(a[3]), "r"(b0), "r"(b1));
}

#define CPA16(dst, src) \
    asm volatile("cp.async.cg.shared.global [%0], [%1], 16;" \
                 :: "r"(dst), "l"(src) : "memory")

// ------------- fused: x -> bf16 hi/lo split  +  dt -> da/db -------------
__device__ __forceinline__ float softplusf(float a) {
    return (a > 20.f) ? a : log1pf(expf(a));
}

__global__ __launch_bounds__(256) void dtconv_kernel(
    const float* __restrict__ x, const float* __restrict__ dtw,
    const float* __restrict__ dtb, const float* __restrict__ Alog)
{
    int tid = threadIdx.x;
    int row_local = tid >> 6;
    int lane = tid & 31;
    int t64 = tid & 63;
    int c4 = t64 << 2;
    int r = blockIdx.x * 4 + row_local;
    size_t idx = (size_t)r * 256 + c4;

    float4 v = *(const float4*)(x + idx);
    uint2 hv, lv; split4(v, hv, lv);
    *(uint2*)(g_ahi + idx) = hv;
    *(uint2*)(g_alo + idx) = lv;

    int d4 = c4 & 31;
    float t0 = v.x * dtw[d4] + v.y * dtw[d4 + 1] + v.z * dtw[d4 + 2] + v.w * dtw[d4 + 3];
    float t1 = v.x * dtw[32 + d4] + v.y * dtw[32 + d4 + 1]
             + v.z * dtw[32 + d4 + 2] + v.w * dtw[32 + d4 + 3];
#pragma unroll
    for (int off = 4; off; off >>= 1) {
        t0 += __shfl_down_sync(0xffffffffu, t0, off);
        t1 += __shfl_down_sync(0xffffffffu, t1, off);
    }
    if ((lane & 7) == 0) {
        int n = t64 >> 3;
        int w = r & 63, h = (r >> 6) & 63, b = r >> 12;
        float bias = dtb[n];
        float Aa = -expf(Alog[n]);
        float da = softplusf(t0 + bias) * Aa;
        float db = softplusf(t1 + bias) * Aa;
        g_da[((b * 64 + h) * 8 + n) * 64 + w] = da;
        g_db[((b * 64 + w) * 8 + n) * 64 + h] = db;
    }
}

__global__ __launch_bounds__(256) void convW_kernel(
    const float* __restrict__ wq, const float* __restrict__ wk,
    const float* __restrict__ wv, const float* __restrict__ wo)
{
    const float* src = (blockIdx.y == 0) ? wq : (blockIdx.y == 1) ? wk
                     : (blockIdx.y == 2) ? wv : wo;
    size_t base = (size_t)blockIdx.y * 65536;
    size_t i = ((size_t)blockIdx.x * 256 + threadIdx.x) * 4;
    float4 v = *(const float4*)(src + i);
    uint2 hv, lv; split4(v, hv, lv);
    *(uint2*)(g_whi + base + i) = hv;
    *(uint2*)(g_wlo + base + i) = lv;
}

// ------------- projection GEMM (fp32 outputs; L2-remap grid) -------------
#define GP 40
#define GMAT 10240
#define GSTG 40960
#define GEMM_SMEM (2*GSTG)

__global__ __launch_bounds__(256, 2) void gemm_mma_kernel(
    const float* __restrict__ b0p, const float* __restrict__ b1p,
    const float* __restrict__ b2p, float* __restrict__ dout,
    int mode, float scaleK,
    const float* __restrict__ sinp, const float* __restrict__ cosp)
{
    extern __shared__ char gsm[];
    int z, col;
    if (mode == 0) { z = blockIdx.x >> 1; col = blockIdx.x & 1; }
    else           { z = 3;               col = blockIdx.x; }
    float* outp;
    const float* bias;
    float scale = 1.0f;
    bool do_rope = false;
    if (mode == 0) {
        if (z == 0)      { outp = g_q; bias = b0p; do_rope = true; }
        else if (z == 1) { outp = g_k; bias = b1p; do_rope = true; scale = scaleK; }
        else             { outp = g_v; bias = b2p; }
    } else { outp = dout; bias = b0p; }
    const __nv_bfloat16* Whi = g_whi + (size_t)z * 65536;
    const __nv_bfloat16* Wlo = g_wlo + (size_t)z * 65536;

    int tid = threadIdx.x;
    int lane = tid & 31, wid = tid >> 5;
    int warp_m = wid >> 2, warp_n = wid & 3;
    int row0 = blockIdx.y * 128;
    int n0 = col * 128;

    int r0i = tid >> 2, q0 = tid & 3;
    int r1i = (tid + 256) >> 2, q1 = tid & 3;
    uint32_t st0 = (uint32_t)(r0i * GP + q0 * 8) * 2;
    uint32_t st1 = (uint32_t)(r1i * GP + q1 * 8) * 2;
    uint32_t gsb = smem_u32(gsm);

    float acc[4][4][4];
#pragma unroll
    for (int i = 0; i < 4; i++)
#pragma unroll
        for (int j = 0; j < 4; j++)
#pragma unroll
            for (int e = 0; e < 4; e++) acc[i][j][e] = 0.f;

    uint32_t a_off[4], b_off[2];
#pragma unroll
    for (int mi = 0; mi < 4; mi++) {
        int row = warp_m * 64 + mi * 16 + (lane & 15);
        int colb = ((lane >> 4) & 1) << 3;
        a_off[mi] = (uint32_t)(row * GP + colb) * 2;
    }
#pragma unroll
    for (int p = 0; p < 2; p++) {
        int m = lane >> 3;
        int nrow = warp_n * 32 + p * 16 + ((m >> 1) << 3) + (lane & 7);
        int colb = (m & 1) << 3;
        b_off[p] = (uint32_t)(nrow * GP + colb) * 2;
    }

    auto issue = [&](int kc) {
        uint32_t sb = gsb + (kc & 1) * GSTG;
        int kn = kc * 32;
        size_t a0 = (size_t)(row0 + r0i) * 256 + kn + q0 * 8;
        size_t a1 = (size_t)(row0 + r1i) * 256 + kn + q1 * 8;
        size_t b0 = (size_t)(n0 + r0i) * 256 + kn + q0 * 8;
        size_t b1 = (size_t)(n0 + r1i) * 256 + kn + q1 * 8;
        CPA16(sb + 0*GMAT + st0, (const void*)(g_ahi + a0));
        CPA16(sb + 0*GMAT + st1, (const void*)(g_ahi + a1));
        CPA16(sb + 1*GMAT + st0, (const void*)(g_alo + a0));
        CPA16(sb + 1*GMAT + st1, (const void*)(g_alo + a1));
        CPA16(sb + 2*GMAT + st0, (const void*)(Whi + b0));
        CPA16(sb + 2*GMAT + st1, (const void*)(Whi + b1));
        CPA16(sb + 3*GMAT + st0, (const void*)(Wlo + b0));
        CPA16(sb + 3*GMAT + st1, (const void*)(Wlo + b1));
        asm volatile("cp.async.commit_group;" ::: "memory");
    };

    issue(0);
    for (int kc = 0; kc < 8; kc++) {
        if (kc < 7) {
            issue(kc + 1);
            asm volatile("cp.async.wait_group 1;" ::: "memory");
        } else {
            asm volatile("cp.async.wait_group 0;" ::: "memory");
        }
        __syncthreads();
        uint32_t sb = gsb + (kc & 1) * GSTG;
#pragma unroll
        for (int ks = 0; ks < 2; ks++) {
            uint32_t kb = (uint32_t)(ks * 16) * 2;
            uint32_t bh[2][4], bl[2][4];
#pragma unroll
            for (int p = 0; p < 2; p++) {
                ldm4(sb + 2*GMAT + b_off[p] + kb, bh[p][0], bh[p][1], bh[p][2], bh[p][3]);
                ldm4(sb + 3*GMAT + b_off[p] + kb, bl[p][0], bl[p][1], bl[p][2], bl[p][3]);
            }
#pragma unroll
            for (int mi = 0; mi < 4; mi++) {
                uint32_t ah[4], al[4];
                ldm4(sb + 0*GMAT + a_off[mi] + kb, ah[0], ah[1], ah[2], ah[3]);
                ldm4(sb + 1*GMAT + a_off[mi] + kb, al[0], al[1], al[2], al[3]);
#pragma unroll
                for (int nj = 0; nj < 4; nj++) {
                    int p = nj >> 1, h = (nj & 1) << 1;
                    mma16816(acc[mi][nj], ah, bh[p][h], bh[p][h + 1]);
                    mma16816(acc[mi][nj], ah, bl[p][h], bl[p][h + 1]);
                    mma16816(acc[mi][nj], al, bh[p][h], bh[p][h + 1]);
                }
            }
        }
        __syncthreads();
    }

#pragma unroll
    for (int mi = 0; mi < 4; mi++) {
        int rbase = row0 + warp_m * 64 + mi * 16 + (lane >> 2);
        int hw0 = rbase & 4095;
        int hw8 = (rbase + 8) & 4095;
#pragma unroll
        for (int nj = 0; nj < 4; nj++) {
            int c = n0 + warp_n * 32 + nj * 8 + ((lane & 3) << 1);
            float b0 = __ldg(bias + c), b1 = __ldg(bias + c + 1);
            float2 o0, o1;
            o0.x = (acc[mi][nj][0] + b0) * scale;
            o0.y = (acc[mi][nj][1] + b1) * scale;
            o1.x = (acc[mi][nj][2] + b0) * scale;
            o1.y = (acc[mi][nj][3] + b1) * scale;
            if (do_rope) {
                int d0 = c & 31;
                float s0 = __ldg(sinp + hw0 * 32 + d0);
                float s1 = __ldg(sinp + hw0 * 32 + d0 + 1);
                float c0v = __ldg(cosp + hw0 * 32 + d0);
                float c1v = __ldg(cosp + hw0 * 32 + d0 + 1);
                float xe = o0.x, xo = o0.y;
                o0.x = xe * c0v - xo * s0;
                o0.y = xo * c1v + xe * s1;
                float s0b = __ldg(sinp + hw8 * 32 + d0);
                float s1b = __ldg(sinp + hw8 * 32 + d0 + 1);
                float c0b = __ldg(cosp + hw8 * 32 + d0);
                float c1b = __ldg(cosp + hw8 * 32 + d0 + 1);
                float xe1 = o1.x, xo1 = o1.y;
                o1.x = xe1 * c0b - xo1 * s0b;
                o1.y = xo1 * c1b + xe1 * s1b;
            }
            *(float2*)(outp + (size_t)rbase * 256 + c) = o0;
            *(float2*)(outp + (size_t)(rbase + 8) * 256 + c) = o1;
        }
    }
}

// ---------------- LePE depthwise 5x5 conv ----------------
__global__ __launch_bounds__(256) void lepe_kernel(
    const float* __restrict__ lw, const float* __restrict__ lb)
{
    int blk = blockIdx.x;
    int whalf = blk & 1;
    int h = (blk >> 1) & 63;
    int b = blk >> 7;
    int c = threadIdx.x;

    float wt[5][5];
    const float* vrow[5];
    bool rv[5];
#pragma unroll
    for (int ki = 0; ki < 5; ki++) {
        int hh = h + ki - 2;
        rv[ki] = ((unsigned)hh < 64u);
        vrow[ki] = g_v + ((size_t)((b * 64 + (rv[ki] ? hh : 0)) * 64)) * 256 + c;
#pragma unroll
        for (int kj = 0; kj < 5; kj++)
            wt[ki][kj] = __ldg(lw + (ki * 5 + kj) * 256 + c);
    }
    float lbv = __ldg(lb + c);

    float win[5][5];
    int w0 = whalf * 32;
#pragma unroll
    for (int dj = 0; dj < 4; dj++) {
        int col = w0 - 2 + dj;
        bool cv = ((unsigned)col < 64u);
#pragma unroll
        for (int ki = 0; ki < 5; ki++)
            win[ki][dj] = (rv[ki] && cv) ? __ldg(vrow[ki] + col * 256) : 0.f;
    }

    float* outb = g_lepe + ((size_t)((b * 64 + h) * 64)) * 256 + c;
#pragma unroll
    for (int it = 0; it < 32; it++) {
        int w = w0 + it;
        int col = w + 2;
        bool cv = (col < 64);
        const int slot = (it + 4) % 5;
#pragma unroll
        for (int ki = 0; ki < 5; ki++)
            win[ki][slot] = (rv[ki] && cv) ? __ldg(vrow[ki] + col * 256) : 0.f;
        float acc = lbv;
#pragma unroll
        for (int ki = 0; ki < 5; ki++)
#pragma unroll
            for (int kj = 0; kj < 5; kj++)
                acc += win[ki][(it + kj) % 5] * wt[ki][kj];
        outb[w * 256] = acc;
    }
}

// ---------------- attention: 4-warp register-resident S/P ----------------
#define AQ_HI 0
#define AQ_LO 5120
#define AK_HI 10240
#define AK_LO 15360
#define AV_HI 20480
#define AV_LO 25600
#define AW_HI 30720
#define AW_LO 35840
#define W_CS  30720
#define H_CS  40960
#define ATTN_SMEM_W 30976
#define ATTN_SMEM_H 41216

__device__ __forceinline__ void cs_scan(const float* __restrict__ src, float* cs, int tid)
{
    if (tid < 32) {
        float a = src[tid], b = src[tid + 32];
#pragma unroll
        for (int off = 1; off < 32; off <<= 1) {
            float t = __shfl_up_sync(0xffffffffu, a, off);
            if (tid >= off) a += t;
        }
        float tot = __shfl_sync(0xffffffffu, a, 31);
#pragma unroll
        for (int off = 1; off < 32; off <<= 1) {
            float t = __shfl_up_sync(0xffffffffu, b, off);
            if (tid >= off) b += t;
        }
        cs[tid] = a;
        cs[tid + 32] = b + tot;
    }
}

__device__ __forceinline__ void s_reg(uint32_t sbase, int lane, int w, float sacc[8][4])
{
    uint32_t a_off = (uint32_t)((w * 16 + (lane & 15)) * GP + (((lane >> 4) & 1) << 3)) * 2;
    int m = lane >> 3;
    uint32_t b_base = (uint32_t)((((m >> 1) << 3) + (lane & 7)) * GP + ((m & 1) << 3)) * 2;
#pragma unroll
    for (int ks = 0; ks < 2; ks++) {
        uint32_t kb = (uint32_t)ks * 32;
        uint32_t ah[4], al[4];
        ldm4(sbase + AQ_HI + a_off + kb, ah[0], ah[1], ah[2], ah[3]);
        ldm4(sbase + AQ_LO + a_off + kb, al[0], al[1], al[2], al[3]);
#pragma unroll
        for (int jb = 0; jb < 4; jb++) {
            uint32_t boff = b_base + (uint32_t)(jb * 16 * GP) * 2 + kb;
            uint32_t bh[4], bl[4];
            ldm4(sbase + AK_HI + boff, bh[0], bh[1], bh[2], bh[3]);
            ldm4(sbase + AK_LO + boff, bl[0], bl[1], bl[2], bl[3]);
#pragma unroll
            for (int half = 0; half < 2; half++) {
                float* d = sacc[jb * 2 + half];
                int h2 = half * 2;
                mma16816(d, ah, bh[h2], bh[h2 + 1]);
                mma16816(d, ah, bl[h2], bl[h2 + 1]);
                mma16816(d, al, bh[h2], bh[h2 + 1]);
            }
        }
    }
}

__device__ __forceinline__ void mask_softmax_reg(int lane, int w, const float* cs,
                                                 float sacc[8][4])
{
    int gr = lane >> 2, gc2 = (lane & 3) << 1;
    int r0 = w * 16 + gr, r1 = r0 + 8;
    float cr0 = cs[r0], cr1 = cs[r1];
#pragma unroll
    for (int nj = 0; nj < 8; nj++) {
        int c0 = nj * 8 + gc2;
        float cc0 = cs[c0], cc1 = cs[c0 + 1];
        sacc[nj][0] += (r0 >= c0)     ? cr0 - cc0 : cc0 - cr0;
        sacc[nj][1] += (r0 >= c0 + 1) ? cr0 - cc1 : cc1 - cr0;
        sacc[nj][2] += (r1 >= c0)     ? cr1 - cc0 : cc0 - cr1;
        sacc[nj][3] += (r1 >= c0 + 1) ? cr1 - cc1 : cc1 - cr1;
    }
    float m0 = -1e30f, m1 = -1e30f;
#pragma unroll
    for (int nj = 0; nj < 8; nj++) {
        m0 = fmaxf(m0, fmaxf(sacc[nj][0], sacc[nj][1]));
        m1 = fmaxf(m1, fmaxf(sacc[nj][2], sacc[nj][3]));
    }
    m0 = fmaxf(m0, __shfl_xor_sync(0xffffffffu, m0, 1));
    m0 = fmaxf(m0, __shfl_xor_sync(0xffffffffu, m0, 2));
    m1 = fmaxf(m1, __shfl_xor_sync(0xffffffffu, m1, 1));
    m1 = fmaxf(m1, __shfl_xor_sync(0xffffffffu, m1, 2));
    float s0 = 0.f, s1 = 0.f;
#pragma unroll
    for (int nj = 0; nj < 8; nj++) {
        sacc[nj][0] = __expf(sacc[nj][0] - m0); s0 += sacc[nj][0];
        sacc[nj][1] = __expf(sacc[nj][1] - m0); s0 += sacc[nj][1];
        sacc[nj][2] = __expf(sacc[nj][2] - m1); s1 += sacc[nj][2];
        sacc[nj][3] = __expf(sacc[nj][3] - m1); s1 += sacc[nj][3];
    }
    s0 += __shfl_xor_sync(0xffffffffu, s0, 1);
    s0 += __shfl_xor_sync(0xffffffffu, s0, 2);
    s1 += __shfl_xor_sync(0xffffffffu, s1, 1);
    s1 += __shfl_xor_sync(0xffffffffu, s1, 2);
    float i0 = 1.f / s0, i1 = 1.f / s1;
#pragma unroll
    for (int nj = 0; nj < 8; nj++) {
        sacc[nj][0] *= i0; sacc[nj][1] *= i0;
        sacc[nj][2] *= i1; sacc[nj][3] *= i1;
    }
}

// full 3-term PV (P hi+lo in registers)
__device__ __forceinline__ void pv_reg(uint32_t bhi, uint32_t blo, int lane,
                                       const uint32_t ph[8][2], const uint32_t pl[8][2],
                                       float facc[4][4])
{
    int g = lane >> 3, j8 = lane & 7;
    uint32_t b_base = (uint32_t)(((g & 1) * 8 + j8) * GP + ((g >> 1) << 3)) * 2;
#pragma unroll
    for (int kc = 0; kc < 4; kc++) {
        uint32_t ah[4] = {ph[2*kc][0], ph[2*kc][1], ph[2*kc+1][0], ph[2*kc+1][1]};
        uint32_t al[4] = {pl[2*kc][0], pl[2*kc][1], pl[2*kc+1][0], pl[2*kc+1][1]};
        uint32_t krow = (uint32_t)(kc * 16 * GP) * 2;
#pragma unroll
        for (int cg = 0; cg < 2; cg++) {
            uint32_t boff = b_base + krow + (uint32_t)(cg * 16) * 2;
            uint32_t bh[4], bl[4];
            ldm4t(bhi + boff, bh[0], bh[1], bh[2], bh[3]);
            ldm4t(blo + boff, bl[0], bl[1], bl[2], bl[3]);
#pragma unroll
            for (int half = 0; half < 2; half++) {
                float* d = facc[cg * 2 + half];
                int h2 = half * 2;
                mma16816(d, ah, bh[h2], bh[h2 + 1]);
                mma16816(d, ah, bl[h2], bl[h2 + 1]);
                mma16816(d, al, bh[h2], bh[h2 + 1]);
            }
        }
    }
}

// 2-term PV (P hi only): D += Ph*Vh + Ph*Vl
__device__ __forceinline__ void pv_reg_hi(uint32_t bhi, uint32_t blo, int lane,
                                          const uint32_t ph[8][2], float facc[4][4])
{
    int g = lane >> 3, j8 = lane & 7;
    uint32_t b_base = (uint32_t)(((g & 1) * 8 + j8) * GP + ((g >> 1) << 3)) * 2;
#pragma unroll
    for (int kc = 0; kc < 4; kc++) {
        uint32_t ah[4] = {ph[2*kc][0], ph[2*kc][1], ph[2*kc+1][0], ph[2*kc+1][1]};
        uint32_t krow = (uint32_t)(kc * 16 * GP) * 2;
#pragma unroll
        for (int cg = 0; cg < 2; cg++) {
            uint32_t boff = b_base + krow + (uint32_t)(cg * 16) * 2;
            uint32_t bh[4], bl[4];
            ldm4t(bhi + boff, bh[0], bh[1], bh[2], bh[3]);
            ldm4t(blo + boff, bl[0], bl[1], bl[2], bl[3]);
#pragma unroll
            for (int half = 0; half < 2; half++) {
                float* d = facc[cg * 2 + half];
                int h2 = half * 2;
                mma16816(d, ah, bh[h2], bh[h2 + 1]);
                mma16816(d, ah, bl[h2], bl[h2 + 1]);
            }
        }
    }
}

__global__ __launch_bounds__(128) void attn_w_kernel(void)
{
    extern __shared__ char sm[];
    int blk = blockIdx.x;
    int n = blk & 7;
    int h = (blk >> 3) & 63;
    int b = blk >> 9;
    int tid = threadIdx.x, lane = tid & 31, w = tid >> 5;
    int qbase = ((b * 64 + h) * 64) * 256 + n * 32;
    float* cs = (float*)(sm + W_CS);
    uint32_t sbase = smem_u32(sm);

    for (int e = tid; e < 512; e += 128) {
        int i = e >> 3, d4 = (e & 7) << 2;
        float4 qv = *(const float4*)(g_q + qbase + i * 256 + d4);
        float4 kv = *(const float4*)(g_k + qbase + i * 256 + d4);
        float4 vv = *(const float4*)(g_v + qbase + i * 256 + d4);
        uint2 hv, lv;
        uint32_t so = (uint32_t)(i * GP + d4) * 2;
        split4(qv, hv, lv);
        *(uint2*)(sm + AQ_HI + so) = hv; *(uint2*)(sm + AQ_LO + so) = lv;
        split4(kv, hv, lv);
        *(uint2*)(sm + AK_HI + so) = hv; *(uint2*)(sm + AK_LO + so) = lv;
        split4(vv, hv, lv);
        *(uint2*)(sm + AV_HI + so) = hv; *(uint2*)(sm + AV_LO + so) = lv;
    }
    cs_scan(g_da + blk * 64, cs, tid);
    __syncthreads();

    float sacc[8][4];
#pragma unroll
    for (int nj = 0; nj < 8; nj++)
#pragma unroll
        for (int e = 0; e < 4; e++) sacc[nj][e] = 0.f;
    s_reg(sbase, lane, w, sacc);
    mask_softmax_reg(lane, w, cs, sacc);

    // pack P fragments; export HI only
    uint32_t ph[8][2], pl[8][2];
    size_t pbase = (size_t)blk * 2048 + w * 512 + lane;
#pragma unroll
    for (int nj = 0; nj < 8; nj++) {
        ph[nj][0] = packsplit(sacc[nj][0], sacc[nj][1], pl[nj][0]);
        ph[nj][1] = packsplit(sacc[nj][2], sacc[nj][3], pl[nj][1]);
        g_qkwh[pbase + (nj * 2 + 0) * 32] = ph[nj][0];
        g_qkwh[pbase + (nj * 2 + 1) * 32] = ph[nj][1];
    }

    float facc[4][4];
#pragma unroll
    for (int nj = 0; nj < 4; nj++)
#pragma unroll
        for (int e = 0; e < 4; e++) facc[nj][e] = 0.f;
    pv_reg(sbase + AV_HI, sbase + AV_LO, lane, ph, pl, facc);

    float* vwp = g_vw + (size_t)blk * 2048;
    int gr = lane >> 2, gc2 = (lane & 3) << 1;
    int r0 = w * 16 + gr;
#pragma unroll
    for (int nj = 0; nj < 4; nj++) {
        int d0 = nj * 8 + gc2;
        float2 o0 = {facc[nj][0], facc[nj][1]};
        float2 o1 = {facc[nj][2], facc[nj][3]};
        *(float2*)(vwp + r0 * 32 + d0) = o0;
        *(float2*)(vwp + (r0 + 8) * 32 + d0) = o1;
    }
}

__global__ __launch_bounds__(128) void attn_h_kernel(void)
{
    extern __shared__ char sm[];
    int blk = blockIdx.x;
    int n = blk & 7;
    int x = (blk >> 3) & 63;
    int b = blk >> 9;
    int tid = threadIdx.x, lane = tid & 31, w = tid >> 5;
    int qbase = (b * 64 * 64 + x) * 256 + n * 32;
    float* cs = (float*)(sm + H_CS);
    uint32_t sbase = smem_u32(sm);

    for (int e = tid; e < 512; e += 128) {
        int i = e >> 3, d4 = (e & 7) << 2;
        float4 qv = *(const float4*)(g_q + qbase + i * 16384 + d4);
        float4 kv = *(const float4*)(g_k + qbase + i * 16384 + d4);
        float4 vv = *(const float4*)(g_v + qbase + i * 16384 + d4);
        float4 wv = *(const float4*)(g_vw + ((size_t)((b * 64 + i) * 8 + n)) * 2048 + x * 32 + d4);
        uint2 hv, lv;
        uint32_t so = (uint32_t)(i * GP + d4) * 2;
        split4(qv, hv, lv);
        *(uint2*)(sm + AQ_HI + so) = hv; *(uint2*)(sm + AQ_LO + so) = lv;
        split4(kv, hv, lv);
        *(uint2*)(sm + AK_HI + so) = hv; *(uint2*)(sm + AK_LO + so) = lv;
        split4(vv, hv, lv);
        *(uint2*)(sm + AV_HI + so) = hv; *(uint2*)(sm + AV_LO + so) = lv;
        split4(wv, hv, lv);
        *(uint2*)(sm + AW_HI + so) = hv; *(uint2*)(sm + AW_LO + so) = lv;
    }
    cs_scan(g_db + blk * 64, cs, tid);
    __syncthreads();

    float sacc[8][4];
#pragma unroll
    for (int nj = 0; nj < 8; nj++)
#pragma unroll
        for (int e = 0; e < 4; e++) sacc[nj][e] = 0.f;
    s_reg(sbase, lane, w, sacc);
    mask_softmax_reg(lane, w, cs, sacc);

    uint32_t ph[8][2], pl[8][2];
#pragma unroll
    for (int nj = 0; nj < 8; nj++) {
        ph[nj][0] = packsplit(sacc[nj][0], sacc[nj][1], pl[nj][0]);
        ph[nj][1] = packsplit(sacc[nj][2], sacc[nj][3], pl[nj][1]);
    }

    float facc1[4][4], facc2[4][4];
#pragma unroll
    for (int nj = 0; nj < 4; nj++)
#pragma unroll
        for (int e = 0; e < 4; e++) { facc1[nj][e] = 0.f; facc2[nj][e] = 0.f; }
    pv_reg(sbase + AV_HI, sbase + AV_LO, lane, ph, pl, facc1);
    pv_reg(sbase + AW_HI, sbase + AW_LO, lane, ph, pl, facc2);

    float* v2p = g_vh2 + (size_t)blk * 2048;
    int gr = lane >> 2, gc2 = (lane & 3) << 1;
    int r0 = w * 16 + gr;
#pragma unroll
    for (int nj = 0; nj < 4; nj++) {
        int d0 = nj * 8 + gc2;
        float2 o0 = {facc1[nj][0], facc1[nj][1]};
        float2 o1 = {facc1[nj][2], facc1[nj][3]};
        *(float2*)(v2p + r0 * 32 + d0) = o0;
        *(float2*)(v2p + (r0 + 8) * 32 + d0) = o1;
        float2 p0 = {0.5f * facc2[nj][0], 0.5f * facc2[nj][1]};
        float2 p1 = {0.5f * facc2[nj][2], 0.5f * facc2[nj][3]};
        *(float2*)(g_pre + (size_t)((b * 64 + r0) * 64 + x) * 256 + n * 32 + d0) = p0;
        *(float2*)(g_pre + (size_t)((b * 64 + r0 + 8) * 64 + x) * 256 + n * 32 + d0) = p1;
    }
}

// out2: final = pre + 0.5*(qk_w(hi) @ v_h2) + lepe -> bf16 hi/lo split
#define O2_VHI 0
#define O2_VLO 5120
#define OUT2_SMEM 10240

__global__ __launch_bounds__(128) void out2_kernel(void)
{
    extern __shared__ char sm[];
    int blk = blockIdx.x;
    int n = blk & 7;
    int y = (blk >> 3) & 63;
    int b = blk >> 9;
    int tid = threadIdx.x, lane = tid & 31, w = tid >> 5;
    uint32_t sbase = smem_u32(sm);

    uint32_t ph[8][2];
    size_t pbase = (size_t)blk * 2048 + w * 512 + lane;
#pragma unroll
    for (int nj = 0; nj < 8; nj++) {
        ph[nj][0] = g_qkwh[pbase + (nj * 2 + 0) * 32];
        ph[nj][1] = g_qkwh[pbase + (nj * 2 + 1) * 32];
    }

    for (int e = tid; e < 512; e += 128) {
        int j = e >> 3, d4 = (e & 7) << 2;
        float4 vv = *(const float4*)(g_vh2 + ((size_t)((b * 64 + j) * 8 + n)) * 2048 + y * 32 + d4);
        uint2 hv, lv;
        split4(vv, hv, lv);
        uint32_t so = (uint32_t)(j * GP + d4) * 2;
        *(uint2*)(sm + O2_VHI + so) = hv;
        *(uint2*)(sm + O2_VLO + so) = lv;
    }
    __syncthreads();

    float facc[4][4];
#pragma unroll
    for (int nj = 0; nj < 4; nj++)
#pragma unroll
        for (int e = 0; e < 4; e++) facc[nj][e] = 0.f;
    pv_reg_hi(sbase + O2_VHI, sbase + O2_VLO, lane, ph, facc);

    int gr = lane >> 2, gc2 = (lane & 3) << 1;
    int r0 = w * 16 + gr;
#pragma unroll
    for (int nj = 0; nj < 4; nj++) {
        int d0 = n * 32 + nj * 8 + gc2;
        size_t a0 = (size_t)((b * 64 + y) * 64 + r0) * 256 + d0;
        size_t a1 = (size_t)((b * 64 + y) * 64 + r0 + 8) * 256 + d0;
        float2 pr0 = *(float2*)(g_pre + a0);
        float2 le0 = *(float2*)(g_lepe + a0);
        float2 pr1 = *(float2*)(g_pre + a1);
        float2 le1 = *(float2*)(g_lepe + a1);
        float fx0 = pr0.x + 0.5f * facc[nj][0] + le0.x;
        float fy0 = pr0.y + 0.5f * facc[nj][1] + le0.y;
        float fx1 = pr1.x + 0.5f * facc[nj][2] + le1.x;
        float fy1 = pr1.y + 0.5f * facc[nj][3] + le1.y;
        uint32_t lo0, lo1;
        uint32_t hi0 = packsplit(fx0, fy0, lo0);
        uint32_t hi1 = packsplit(fx1, fy1, lo1);
        *(uint32_t*)(g_ahi + a0) = hi0;
        *(uint32_t*)(g_alo + a0) = lo0;
        *(uint32_t*)(g_ahi + a1) = hi1;
        *(uint32_t*)(g_alo + a1) = lo1;
    }
}

// ---------------- launch ----------------
extern "C" void kernel_launch(void* const* d_in, const int* in_sizes, int n_in,
                              void* d_out, int out_size)
{
    const float* x    = (const float*)d_in[0];
    const float* sinp = (const float*)d_in[1];
    const float* cosp = (const float*)d_in[2];
    const float* Wq   = (const float*)d_in[3];
    const float* bq   = (const float*)d_in[4];
    const float* Wk   = (const float*)d_in[5];
    const float* bk   = (const float*)d_in[6];
    const float* Wv   = (const float*)d_in[7];
    const float* bv   = (const float*)d_in[8];
    const float* Wo   = (const float*)d_in[9];
    const float* bo   = (const float*)d_in[10];
    const float* lw   = (const float*)d_in[11];
    const float* lb   = (const float*)d_in[12];
    const float* dtw  = (const float*)d_in[13];
    const float* dtb  = (const float*)d_in[14];
    const float* Alog = (const float*)d_in[15];
    float* out = (float*)d_out;

    const float scaling = 0.17677669529663687f;   // 32^-0.5

    cudaFuncSetAttribute(gemm_mma_kernel,
                         cudaFuncAttributeMaxDynamicSharedMemorySize, GEMM_SMEM);

    convW_kernel<<<dim3(64, 4), 256>>>(Wq, Wk, Wv, Wo);               // 0
    dtconv_kernel<<<NROW / 4, 256>>>(x, dtw, dtb, Alog);              // 1

    gemm_mma_kernel<<<dim3(6, 512), 256, GEMM_SMEM>>>(
        bq, bk, bv, nullptr, 0, scaling, sinp, cosp);                 // 2

    attn_w_kernel<<<Bn * Hn * Nn, 128, ATTN_SMEM_W>>>();              // 3 <- profiled
    attn_h_kernel<<<Bn * Wn * Nn, 128, ATTN_SMEM_H>>>();              // 4

    lepe_kernel<<<Bn * Hn * 2, 256>>>(lw, lb);                        // 5

    out2_kernel<<<Bn * Hn * Nn, 128, OUT2_SMEM>>>();                  // 6

    gemm_mma_kernel<<<dim3(2, 512), 256, GEMM_SMEM>>>(
        bo, nullptr, nullptr, out, 1, 1.0f, sinp, cosp);              // 7
}